// round 4
// baseline (speedup 1.0000x reference)
#include <cuda_runtime.h>
#include <math.h>
#include <stdint.h>

// ---------------- problem constants ----------------
#define BATCH 4
#define IMGH  64
#define IMGW  64
#define CDIM  768
#define WS    14
#define TOK   196
#define NH    12
#define HD    64
#define NWH   5
#define NWW   5
#define BW    100
#define ROWS_WIN 19600
#define ROWS_IMG 16384
#define QKVN  2304
#define FFN   3072

// ---------------- scratch ----------------
__device__ float g_win[(size_t)ROWS_WIN * CDIM];
__device__ float g_qkv[(size_t)ROWS_WIN * QKVN];
__device__ float g_att[(size_t)ROWS_WIN * CDIM];
__device__ float g_x2 [(size_t)ROWS_IMG * CDIM];
__device__ float g_yln[(size_t)ROWS_IMG * CDIM];
__device__ float g_y1 [(size_t)ROWS_IMG * FFN];
__device__ float g_wqkv[(size_t)CDIM * QKVN];
__device__ float g_wproj[(size_t)CDIM * CDIM];
__device__ float g_wfc1[(size_t)CDIM * FFN];
__device__ float g_wfc2[(size_t)FFN * CDIM];

// ---------------- helpers ----------------
__device__ __forceinline__ float tf32r(float x) {
    uint32_t u;
    asm("cvt.rna.tf32.f32 %0, %1;" : "=r"(u) : "f"(x));
    return __uint_as_float(u);
}
__device__ __forceinline__ uint32_t smem_u32(const void* p) {
    uint32_t a;
    asm("{ .reg .u64 t; cvta.to.shared.u64 t, %1; cvt.u32.u64 %0, t; }" : "=r"(a) : "l"(p));
    return a;
}
__device__ __forceinline__ void cp16(void* sdst, const void* gsrc, int bytes) {
    uint32_t sa = smem_u32(sdst);
    asm volatile("cp.async.cg.shared.global [%0], [%1], 16, %2;" :: "r"(sa), "l"(gsrc), "r"(bytes));
}
#define CP_COMMIT() asm volatile("cp.async.commit_group;")

__device__ __forceinline__ void mma_tf32(float c[4], const uint32_t a[4], const uint32_t b[2]) {
    asm volatile(
        "mma.sync.aligned.m16n8k8.row.col.f32.tf32.tf32.f32 "
        "{%0,%1,%2,%3}, {%4,%5,%6,%7}, {%8,%9}, {%0,%1,%2,%3};"
        : "+f"(c[0]), "+f"(c[1]), "+f"(c[2]), "+f"(c[3])
        : "r"(a[0]), "r"(a[1]), "r"(a[2]), "r"(a[3]), "r"(b[0]), "r"(b[1]));
}

// ---------------- weight tf32 rounding ----------------
__global__ void round_tf32_kernel(const float* __restrict__ in, float* __restrict__ out, int n4) {
    int i = blockIdx.x * blockDim.x + threadIdx.x;
    if (i >= n4) return;
    float4 f = ((const float4*)in)[i];
    f.x = tf32r(f.x); f.y = tf32r(f.y); f.z = tf32r(f.z); f.w = tf32r(f.w);
    ((float4*)out)[i] = f;
}

// ---------------- LN1 + window partition ----------------
__global__ void ln1_win_kernel(const float* __restrict__ x,
                               const float* __restrict__ g,
                               const float* __restrict__ b,
                               float* __restrict__ out_) {
    int warp = (blockIdx.x * blockDim.x + threadIdx.x) >> 5;
    int lane = threadIdx.x & 31;
    if (warp >= ROWS_WIN) return;
    int r = warp;
    int bw = r / TOK, t = r % TOK;
    int bb = bw / (NWH * NWW), rem = bw % (NWH * NWW);
    int wh = rem / NWW, ww = rem % NWW;
    int i = t / WS, j = t % WS;
    int h = wh * WS + i, w = ww * WS + j;
    float* out = out_ + (size_t)r * CDIM;
    if (h >= IMGH || w >= IMGW) {
        float4 z = make_float4(0.f, 0.f, 0.f, 0.f);
        #pragma unroll
        for (int q = 0; q < 6; q++) *(float4*)(out + lane * 4 + q * 128) = z;
        return;
    }
    const float* row = x + ((size_t)(bb * IMGH + h) * IMGW + w) * CDIM;
    float v[24];
    float s = 0.f;
    #pragma unroll
    for (int q = 0; q < 6; q++) {
        float4 f = *(const float4*)(row + lane * 4 + q * 128);
        v[q*4+0] = f.x; v[q*4+1] = f.y; v[q*4+2] = f.z; v[q*4+3] = f.w;
        s += f.x + f.y + f.z + f.w;
    }
    #pragma unroll
    for (int o = 16; o > 0; o >>= 1) s += __shfl_xor_sync(0xffffffffu, s, o);
    float mean = s * (1.0f / CDIM);
    float ss = 0.f;
    #pragma unroll
    for (int q = 0; q < 24; q++) { float d = v[q] - mean; ss += d * d; }
    #pragma unroll
    for (int o = 16; o > 0; o >>= 1) ss += __shfl_xor_sync(0xffffffffu, ss, o);
    float rstd = rsqrtf(ss * (1.0f / CDIM) + 1e-6f);
    #pragma unroll
    for (int q = 0; q < 6; q++) {
        int c = lane * 4 + q * 128;
        float4 gg = *(const float4*)(g + c);
        float4 bb4 = *(const float4*)(b + c);
        float4 o4;
        o4.x = tf32r((v[q*4+0] - mean) * rstd * gg.x + bb4.x);
        o4.y = tf32r((v[q*4+1] - mean) * rstd * gg.y + bb4.y);
        o4.z = tf32r((v[q*4+2] - mean) * rstd * gg.z + bb4.z);
        o4.w = tf32r((v[q*4+3] - mean) * rstd * gg.w + bb4.w);
        *(float4*)(out + c) = o4;
    }
}

// ---------------- LN2 ----------------
__global__ void ln2_kernel(const float* __restrict__ x,
                           const float* __restrict__ g,
                           const float* __restrict__ b,
                           float* __restrict__ out_) {
    int warp = (blockIdx.x * blockDim.x + threadIdx.x) >> 5;
    int lane = threadIdx.x & 31;
    if (warp >= ROWS_IMG) return;
    const float* row = x + (size_t)warp * CDIM;
    float* out = out_ + (size_t)warp * CDIM;
    float v[24];
    float s = 0.f;
    #pragma unroll
    for (int q = 0; q < 6; q++) {
        float4 f = *(const float4*)(row + lane * 4 + q * 128);
        v[q*4+0] = f.x; v[q*4+1] = f.y; v[q*4+2] = f.z; v[q*4+3] = f.w;
        s += f.x + f.y + f.z + f.w;
    }
    #pragma unroll
    for (int o = 16; o > 0; o >>= 1) s += __shfl_xor_sync(0xffffffffu, s, o);
    float mean = s * (1.0f / CDIM);
    float ss = 0.f;
    #pragma unroll
    for (int q = 0; q < 24; q++) { float d = v[q] - mean; ss += d * d; }
    #pragma unroll
    for (int o = 16; o > 0; o >>= 1) ss += __shfl_xor_sync(0xffffffffu, ss, o);
    float rstd = rsqrtf(ss * (1.0f / CDIM) + 1e-6f);
    #pragma unroll
    for (int q = 0; q < 6; q++) {
        int c = lane * 4 + q * 128;
        float4 gg = *(const float4*)(g + c);
        float4 bb4 = *(const float4*)(b + c);
        float4 o4;
        o4.x = tf32r((v[q*4+0] - mean) * rstd * gg.x + bb4.x);
        o4.y = tf32r((v[q*4+1] - mean) * rstd * gg.y + bb4.y);
        o4.z = tf32r((v[q*4+2] - mean) * rstd * gg.z + bb4.z);
        o4.w = tf32r((v[q*4+3] - mean) * rstd * gg.w + bb4.w);
        *(float4*)(out + c) = o4;
    }
}

// ---------------- TF32 mma.sync GEMM: CTA 128x256, warp 64x64, 4-stage cp.async ----------------
// A [M][K] row-major, B [K][N] row-major (both pre-rounded to tf32).
// EPI: 0=bias; 1=bias+gelu+tf32r; 2=bias+window-reverse scatter+residual; 3=bias+residual
#define ASTR 20            // floats per A row slab (16 + 4 pad)
#define BSTR 264           // floats per B k-row (256 + 8 pad)
#define A_STAGE (128 * ASTR)
#define B_STAGE (16 * BSTR)
#define NSTAGE 4
#define GEMM_SMEM_BYTES (NSTAGE * (A_STAGE + B_STAGE) * 4)

template<int EPI>
__global__ __launch_bounds__(256, 1)
void tgemm(const float* __restrict__ A, const float* __restrict__ B,
           const float* __restrict__ bias, const float* __restrict__ R,
           float* __restrict__ Cc, int M, int N, int K) {
    extern __shared__ float sm[];
    float* As = sm;                          // [NSTAGE][128][ASTR]
    float* Bs = sm + NSTAGE * A_STAGE;       // [NSTAGE][16][BSTR]

    int tid = threadIdx.x, wid = tid >> 5, lane = tid & 31;
    int g = lane >> 2, c = lane & 3;
    int mw = (wid & 1) * 64, nw = (wid >> 1) * 64;
    int m0 = blockIdx.y * 128, n0 = blockIdx.x * 256;

    float acc[4][8][4];
    #pragma unroll
    for (int i = 0; i < 4; i++)
        #pragma unroll
        for (int j = 0; j < 8; j++)
            #pragma unroll
            for (int q = 0; q < 4; q++) acc[i][j][q] = 0.f;

    int arow = tid >> 1, akseg = (tid & 1) * 8;
    int bkrow = tid >> 4, bnseg = (tid & 15) * 16;

    auto loadStage = [&](int t) {
        int st = t % NSTAGE;
        int k0 = t * 16;
        float* Ad = As + st * A_STAGE;
        int m = m0 + arow;
        bool v = m < M;
        const float* asrc = v ? (A + (size_t)m * K + k0 + akseg) : A;
        cp16(Ad + arow * ASTR + akseg, asrc, v ? 16 : 0);
        cp16(Ad + arow * ASTR + akseg + 4, v ? (asrc + 4) : A, v ? 16 : 0);
        float* Bd = Bs + st * B_STAGE;
        const float* bsrc = B + (size_t)(k0 + bkrow) * N + n0 + bnseg;
        #pragma unroll
        for (int i = 0; i < 4; i++)
            cp16(Bd + bkrow * BSTR + bnseg + 4 * i, bsrc + 4 * i, 16);
        CP_COMMIT();
    };

    int nk = K / 16;
    #pragma unroll
    for (int t = 0; t < NSTAGE - 1; t++) loadStage(t);

    for (int t = 0; t < nk; t++) {
        asm volatile("cp.async.wait_group %0;" :: "n"(NSTAGE - 2) : "memory");
        __syncthreads();
        if (t + NSTAGE - 1 < nk) loadStage(t + NSTAGE - 1);
        else CP_COMMIT();
        const float* a_s = As + (t % NSTAGE) * A_STAGE;
        const float* b_s = Bs + (t % NSTAGE) * B_STAGE;
        #pragma unroll
        for (int kk = 0; kk < 2; kk++) {
            int kb = kk * 8;
            uint32_t af[4][4], bf[8][2];
            #pragma unroll
            for (int tm = 0; tm < 4; tm++) {
                const float* ap = a_s + (mw + tm * 16 + g) * ASTR + kb + c;
                af[tm][0] = __float_as_uint(ap[0]);
                af[tm][1] = __float_as_uint(ap[8 * ASTR]);
                af[tm][2] = __float_as_uint(ap[4]);
                af[tm][3] = __float_as_uint(ap[8 * ASTR + 4]);
            }
            #pragma unroll
            for (int tn = 0; tn < 8; tn++) {
                const float* bp = b_s + (kb + c) * BSTR + nw + tn * 8 + g;
                bf[tn][0] = __float_as_uint(bp[0]);
                bf[tn][1] = __float_as_uint(bp[4 * BSTR]);
            }
            #pragma unroll
            for (int tm = 0; tm < 4; tm++)
                #pragma unroll
                for (int tn = 0; tn < 8; tn++)
                    mma_tf32(acc[tm][tn], af[tm], bf[tn]);
        }
    }

    // epilogue
    #pragma unroll
    for (int tm = 0; tm < 4; tm++) {
        #pragma unroll
        for (int half = 0; half < 2; half++) {
            int m = m0 + mw + tm * 16 + g + half * 8;
            if (m >= M) continue;
            size_t obase = 0;
            const float* rbase = nullptr;
            bool valid = true;
            if (EPI == 2) {
                int bw = m / TOK, tt = m % TOK;
                int bb = bw / (NWH * NWW), rem = bw % (NWH * NWW);
                int wh = rem / NWW, ww = rem % NWW;
                int ii = tt / WS, jj = tt % WS;
                int h = wh * WS + ii, w = ww * WS + jj;
                if (h >= IMGH || w >= IMGW) valid = false;
                else { obase = ((size_t)(bb * IMGH + h) * IMGW + w) * CDIM; rbase = R + obase; }
            } else {
                obase = (size_t)m * N;
                if (EPI == 3) rbase = R + obase;
            }
            if (!valid) continue;
            #pragma unroll
            for (int tn = 0; tn < 8; tn++) {
                int n = n0 + nw + tn * 8 + 2 * c;
                float v0 = acc[tm][tn][half * 2 + 0] + bias[n];
                float v1 = acc[tm][tn][half * 2 + 1] + bias[n + 1];
                if (EPI == 1) {
                    v0 = tf32r(0.5f * v0 * (1.0f + erff(v0 * 0.7071067811865476f)));
                    v1 = tf32r(0.5f * v1 * (1.0f + erff(v1 * 0.7071067811865476f)));
                } else if (EPI == 2 || EPI == 3) {
                    v0 += rbase[n];
                    v1 += rbase[n + 1];
                }
                *(float2*)(Cc + obase + n) = make_float2(v0, v1);
            }
        }
    }
}

// ---------------- windowed attention ----------------
#define SM_QS   0
#define SM_VS   (TOK * 64)
#define SM_KS   (2 * TOK * 64)
#define SM_RH   (2 * TOK * 64 + TOK * 65)
#define SM_RW   (SM_RH + 27 * 65)
#define SM_PS   (SM_RW + 27 * 65)
#define SM_RHW  (SM_PS + 8 * 200)
#define SM_TOTAL_FLOATS (SM_RHW + 8 * 64)

__global__ void attn_kernel(const float* __restrict__ qkv,
                            const float* __restrict__ relh,
                            const float* __restrict__ relw,
                            float* __restrict__ attout) {
    extern __shared__ float smf[];
    float* qs = smf + SM_QS;
    float* vs = smf + SM_VS;
    float* ks = smf + SM_KS;
    float* Rh = smf + SM_RH;
    float* Rw = smf + SM_RW;
    float* Ps = smf + SM_PS;
    float* rhw = smf + SM_RHW;

    int blk = blockIdx.x;
    int bw = blk / NH, nh = blk % NH;
    int tid = threadIdx.x, lane = tid & 31, warp = tid >> 5;

    const float* base = qkv + (size_t)bw * TOK * QKVN + nh * HD;
    for (int t4 = tid; t4 < TOK * 16; t4 += 256) {
        int t = t4 >> 4, c4 = (t4 & 15) * 4;
        const float* p = base + (size_t)t * QKVN;
        float4 q4 = *(const float4*)(p + c4);
        float4 k4 = *(const float4*)(p + CDIM + c4);
        float4 v4 = *(const float4*)(p + 2 * CDIM + c4);
        *(float4*)(qs + t * 64 + c4) = q4;
        ks[t * 65 + c4 + 0] = k4.x;
        ks[t * 65 + c4 + 1] = k4.y;
        ks[t * 65 + c4 + 2] = k4.z;
        ks[t * 65 + c4 + 3] = k4.w;
        *(float4*)(vs + t * 64 + c4) = v4;
    }
    for (int idx = tid; idx < 27 * 64; idx += 256) {
        int rr = idx >> 6, c = idx & 63;
        Rh[rr * 65 + c] = relh[idx];
        Rw[rr * 65 + c] = relw[idx];
    }
    __syncthreads();

    const float scale = 0.125f;
    for (int qi = warp; qi < TOK; qi += 8) {
        int i = qi / WS, j = qi % WS;
        const float* qrow = qs + qi * 64;

        float rh = 0.f, rw = 0.f;
        if (lane < WS) {
            const float* rhrow = Rh + (i - lane + WS - 1) * 65;
            const float* rwrow = Rw + (j - lane + WS - 1) * 65;
            #pragma unroll 8
            for (int c = 0; c < 64; c++) {
                float qc = qrow[c];
                rh = fmaf(qc, rhrow[c], rh);
                rw = fmaf(qc, rwrow[c], rw);
            }
        }
        rhw[warp * 64 + lane] = rh;
        rhw[warp * 64 + 32 + lane] = rw;
        __syncwarp();

        float accv[7];
        #pragma unroll
        for (int m = 0; m < 7; m++) accv[m] = 0.f;
        #pragma unroll 4
        for (int c = 0; c < 64; c++) {
            float qc = qrow[c];
            #pragma unroll
            for (int m = 0; m < 7; m++) {
                int kj = lane + 32 * m;
                if (kj < TOK) accv[m] = fmaf(qc, ks[kj * 65 + c], accv[m]);
            }
        }
        float s[7];
        #pragma unroll
        for (int m = 0; m < 7; m++) {
            int kj = lane + 32 * m;
            if (kj < TOK) {
                int kk = kj / WS, ll = kj % WS;
                s[m] = accv[m] * scale + rhw[warp * 64 + kk] + rhw[warp * 64 + 32 + ll];
            } else {
                s[m] = -1e30f;
            }
        }
        float mx = -1e30f;
        #pragma unroll
        for (int m = 0; m < 7; m++) mx = fmaxf(mx, s[m]);
        #pragma unroll
        for (int o = 16; o > 0; o >>= 1) mx = fmaxf(mx, __shfl_xor_sync(0xffffffffu, mx, o));
        float p[7], sum = 0.f;
        #pragma unroll
        for (int m = 0; m < 7; m++) { p[m] = __expf(s[m] - mx); sum += p[m]; }
        #pragma unroll
        for (int o = 16; o > 0; o >>= 1) sum += __shfl_xor_sync(0xffffffffu, sum, o);
        float inv = __frcp_rn(sum);
        #pragma unroll
        for (int m = 0; m < 7; m++) {
            int kj = lane + 32 * m;
            if (kj < TOK) Ps[warp * 200 + kj] = p[m] * inv;
        }
        __syncwarp();

        float o0 = 0.f, o1 = 0.f;
        #pragma unroll 4
        for (int kj = 0; kj < TOK; kj++) {
            float pp = Ps[warp * 200 + kj];
            o0 = fmaf(pp, vs[kj * 64 + lane], o0);
            o1 = fmaf(pp, vs[kj * 64 + 32 + lane], o1);
        }
        float* orow = attout + ((size_t)(bw * TOK + qi)) * CDIM + nh * HD;
        orow[lane] = tf32r(o0);
        orow[lane + 32] = tf32r(o1);
        __syncwarp();
    }
}

// ---------------- launch ----------------
extern "C" void kernel_launch(void* const* d_in, const int* in_sizes, int n_in,
                              void* d_out, int out_size) {
    const float* x       = (const float*)d_in[0];
    const float* ln1_g   = (const float*)d_in[1];
    const float* ln1_b   = (const float*)d_in[2];
    const float* w_qkv   = (const float*)d_in[3];
    const float* b_qkv   = (const float*)d_in[4];
    const float* w_proj  = (const float*)d_in[5];
    const float* b_proj  = (const float*)d_in[6];
    const float* relh    = (const float*)d_in[7];
    const float* relw    = (const float*)d_in[8];
    const float* ln2_g   = (const float*)d_in[9];
    const float* ln2_b   = (const float*)d_in[10];
    const float* w_fc1   = (const float*)d_in[11];
    const float* b_fc1   = (const float*)d_in[12];
    const float* w_fc2   = (const float*)d_in[13];
    const float* b_fc2   = (const float*)d_in[14];
    float* out = (float*)d_out;

    float *win, *qkv, *att, *x2, *yln, *y1, *wqkv, *wproj, *wfc1, *wfc2;
    cudaGetSymbolAddress((void**)&win, g_win);
    cudaGetSymbolAddress((void**)&qkv, g_qkv);
    cudaGetSymbolAddress((void**)&att, g_att);
    cudaGetSymbolAddress((void**)&x2,  g_x2);
    cudaGetSymbolAddress((void**)&yln, g_yln);
    cudaGetSymbolAddress((void**)&y1,  g_y1);
    cudaGetSymbolAddress((void**)&wqkv,  g_wqkv);
    cudaGetSymbolAddress((void**)&wproj, g_wproj);
    cudaGetSymbolAddress((void**)&wfc1,  g_wfc1);
    cudaGetSymbolAddress((void**)&wfc2,  g_wfc2);

    const int smem_attn = SM_TOTAL_FLOATS * 4;
    cudaFuncSetAttribute(attn_kernel, cudaFuncAttributeMaxDynamicSharedMemorySize, smem_attn);
    cudaFuncSetAttribute(tgemm<0>, cudaFuncAttributeMaxDynamicSharedMemorySize, GEMM_SMEM_BYTES);
    cudaFuncSetAttribute(tgemm<1>, cudaFuncAttributeMaxDynamicSharedMemorySize, GEMM_SMEM_BYTES);
    cudaFuncSetAttribute(tgemm<2>, cudaFuncAttributeMaxDynamicSharedMemorySize, GEMM_SMEM_BYTES);
    cudaFuncSetAttribute(tgemm<3>, cudaFuncAttributeMaxDynamicSharedMemorySize, GEMM_SMEM_BYTES);

    // round weights to tf32
    round_tf32_kernel<<<(CDIM * QKVN / 4 + 255) / 256, 256>>>(w_qkv, wqkv, CDIM * QKVN / 4);
    round_tf32_kernel<<<(CDIM * CDIM / 4 + 255) / 256, 256>>>(w_proj, wproj, CDIM * CDIM / 4);
    round_tf32_kernel<<<(CDIM * FFN / 4 + 255) / 256, 256>>>(w_fc1, wfc1, CDIM * FFN / 4);
    round_tf32_kernel<<<(FFN * CDIM / 4 + 255) / 256, 256>>>(w_fc2, wfc2, FFN * CDIM / 4);

    // 1) LN1 + window partition
    ln1_win_kernel<<<(ROWS_WIN * 32 + 255) / 256, 256>>>(x, ln1_g, ln1_b, win);

    // 2) QKV GEMM [19600,768]x[768,2304]
    tgemm<0><<<dim3(QKVN / 256, (ROWS_WIN + 127) / 128), 256, GEMM_SMEM_BYTES>>>(
        win, wqkv, b_qkv, nullptr, qkv, ROWS_WIN, QKVN, CDIM);

    // 3) attention
    attn_kernel<<<BW * NH, 256, smem_attn>>>(qkv, relh, relw, att);

    // 4) proj + window reverse + residual
    tgemm<2><<<dim3(CDIM / 256, (ROWS_WIN + 127) / 128), 256, GEMM_SMEM_BYTES>>>(
        att, wproj, b_proj, x, x2, ROWS_WIN, CDIM, CDIM);

    // 5) LN2
    ln2_kernel<<<(ROWS_IMG * 32 + 255) / 256, 256>>>(x2, ln2_g, ln2_b, yln);

    // 6) fc1 + gelu
    tgemm<1><<<dim3(FFN / 256, ROWS_IMG / 128), 256, GEMM_SMEM_BYTES>>>(
        yln, wfc1, b_fc1, nullptr, y1, ROWS_IMG, FFN, CDIM);

    // 7) fc2 + residual
    tgemm<3><<<dim3(CDIM / 256, ROWS_IMG / 128), 256, GEMM_SMEM_BYTES>>>(
        y1, wfc2, b_fc2, x2, out, ROWS_IMG, CDIM, FFN);
}

// round 5
// speedup vs baseline: 1.0540x; 1.0540x over previous
#include <cuda_runtime.h>
#include <math.h>
#include <stdint.h>

// ---------------- problem constants ----------------
#define BATCH 4
#define IMGH  64
#define IMGW  64
#define CDIM  768
#define WS    14
#define TOK   196
#define NH    12
#define HD    64
#define NWH   5
#define NWW   5
#define BW    100
#define ROWS_WIN 19600
#define ROWS_IMG 16384
#define QKVN  2304
#define FFN   3072

// ---------------- scratch ----------------
__device__ float g_win[(size_t)ROWS_WIN * CDIM];
__device__ float g_qkv[(size_t)ROWS_WIN * QKVN];
__device__ float g_att[(size_t)ROWS_WIN * CDIM];
__device__ float g_x2 [(size_t)ROWS_IMG * CDIM];
__device__ float g_yln[(size_t)ROWS_IMG * CDIM];
__device__ float g_y1 [(size_t)ROWS_IMG * FFN];
__device__ float g_wqkv[(size_t)CDIM * QKVN];
__device__ float g_wproj[(size_t)CDIM * CDIM];
__device__ float g_wfc1[(size_t)CDIM * FFN];
__device__ float g_wfc2[(size_t)FFN * CDIM];

// ---------------- helpers ----------------
__device__ __forceinline__ float tf32r(float x) {
    uint32_t u;
    asm("cvt.rna.tf32.f32 %0, %1;" : "=r"(u) : "f"(x));
    return __uint_as_float(u);
}
__device__ __forceinline__ uint32_t smem_u32(const void* p) {
    uint32_t a;
    asm("{ .reg .u64 t; cvta.to.shared.u64 t, %1; cvt.u32.u64 %0, t; }" : "=r"(a) : "l"(p));
    return a;
}
__device__ __forceinline__ void cp16(void* sdst, const void* gsrc, int bytes) {
    uint32_t sa = smem_u32(sdst);
    asm volatile("cp.async.cg.shared.global [%0], [%1], 16, %2;" :: "r"(sa), "l"(gsrc), "r"(bytes));
}
#define CP_COMMIT() asm volatile("cp.async.commit_group;")

__device__ __forceinline__ void mma_tf32(float c[4], const uint32_t a[4], const uint32_t b[2]) {
    asm volatile(
        "mma.sync.aligned.m16n8k8.row.col.f32.tf32.tf32.f32 "
        "{%0,%1,%2,%3}, {%4,%5,%6,%7}, {%8,%9}, {%0,%1,%2,%3};"
        : "+f"(c[0]), "+f"(c[1]), "+f"(c[2]), "+f"(c[3])
        : "r"(a[0]), "r"(a[1]), "r"(a[2]), "r"(a[3]), "r"(b[0]), "r"(b[1]));
}

// ---------------- weight tf32 rounding ----------------
__global__ void round_tf32_kernel(const float* __restrict__ in, float* __restrict__ out, int n4) {
    int i = blockIdx.x * blockDim.x + threadIdx.x;
    if (i >= n4) return;
    float4 f = ((const float4*)in)[i];
    f.x = tf32r(f.x); f.y = tf32r(f.y); f.z = tf32r(f.z); f.w = tf32r(f.w);
    ((float4*)out)[i] = f;
}

// ---------------- LN1 + window partition ----------------
__global__ void ln1_win_kernel(const float* __restrict__ x,
                               const float* __restrict__ g,
                               const float* __restrict__ b,
                               float* __restrict__ out_) {
    int warp = (blockIdx.x * blockDim.x + threadIdx.x) >> 5;
    int lane = threadIdx.x & 31;
    if (warp >= ROWS_WIN) return;
    int r = warp;
    int bw = r / TOK, t = r % TOK;
    int bb = bw / (NWH * NWW), rem = bw % (NWH * NWW);
    int wh = rem / NWW, ww = rem % NWW;
    int i = t / WS, j = t % WS;
    int h = wh * WS + i, w = ww * WS + j;
    float* out = out_ + (size_t)r * CDIM;
    if (h >= IMGH || w >= IMGW) {
        float4 z = make_float4(0.f, 0.f, 0.f, 0.f);
        #pragma unroll
        for (int q = 0; q < 6; q++) *(float4*)(out + lane * 4 + q * 128) = z;
        return;
    }
    const float* row = x + ((size_t)(bb * IMGH + h) * IMGW + w) * CDIM;
    float v[24];
    float s = 0.f;
    #pragma unroll
    for (int q = 0; q < 6; q++) {
        float4 f = *(const float4*)(row + lane * 4 + q * 128);
        v[q*4+0] = f.x; v[q*4+1] = f.y; v[q*4+2] = f.z; v[q*4+3] = f.w;
        s += f.x + f.y + f.z + f.w;
    }
    #pragma unroll
    for (int o = 16; o > 0; o >>= 1) s += __shfl_xor_sync(0xffffffffu, s, o);
    float mean = s * (1.0f / CDIM);
    float ss = 0.f;
    #pragma unroll
    for (int q = 0; q < 24; q++) { float d = v[q] - mean; ss += d * d; }
    #pragma unroll
    for (int o = 16; o > 0; o >>= 1) ss += __shfl_xor_sync(0xffffffffu, ss, o);
    float rstd = rsqrtf(ss * (1.0f / CDIM) + 1e-6f);
    #pragma unroll
    for (int q = 0; q < 6; q++) {
        int c = lane * 4 + q * 128;
        float4 gg = *(const float4*)(g + c);
        float4 bb4 = *(const float4*)(b + c);
        float4 o4;
        o4.x = tf32r((v[q*4+0] - mean) * rstd * gg.x + bb4.x);
        o4.y = tf32r((v[q*4+1] - mean) * rstd * gg.y + bb4.y);
        o4.z = tf32r((v[q*4+2] - mean) * rstd * gg.z + bb4.z);
        o4.w = tf32r((v[q*4+3] - mean) * rstd * gg.w + bb4.w);
        *(float4*)(out + c) = o4;
    }
}

// ---------------- LN2 ----------------
__global__ void ln2_kernel(const float* __restrict__ x,
                           const float* __restrict__ g,
                           const float* __restrict__ b,
                           float* __restrict__ out_) {
    int warp = (blockIdx.x * blockDim.x + threadIdx.x) >> 5;
    int lane = threadIdx.x & 31;
    if (warp >= ROWS_IMG) return;
    const float* row = x + (size_t)warp * CDIM;
    float* out = out_ + (size_t)warp * CDIM;
    float v[24];
    float s = 0.f;
    #pragma unroll
    for (int q = 0; q < 6; q++) {
        float4 f = *(const float4*)(row + lane * 4 + q * 128);
        v[q*4+0] = f.x; v[q*4+1] = f.y; v[q*4+2] = f.z; v[q*4+3] = f.w;
        s += f.x + f.y + f.z + f.w;
    }
    #pragma unroll
    for (int o = 16; o > 0; o >>= 1) s += __shfl_xor_sync(0xffffffffu, s, o);
    float mean = s * (1.0f / CDIM);
    float ss = 0.f;
    #pragma unroll
    for (int q = 0; q < 24; q++) { float d = v[q] - mean; ss += d * d; }
    #pragma unroll
    for (int o = 16; o > 0; o >>= 1) ss += __shfl_xor_sync(0xffffffffu, ss, o);
    float rstd = rsqrtf(ss * (1.0f / CDIM) + 1e-6f);
    #pragma unroll
    for (int q = 0; q < 6; q++) {
        int c = lane * 4 + q * 128;
        float4 gg = *(const float4*)(g + c);
        float4 bb4 = *(const float4*)(b + c);
        float4 o4;
        o4.x = tf32r((v[q*4+0] - mean) * rstd * gg.x + bb4.x);
        o4.y = tf32r((v[q*4+1] - mean) * rstd * gg.y + bb4.y);
        o4.z = tf32r((v[q*4+2] - mean) * rstd * gg.z + bb4.z);
        o4.w = tf32r((v[q*4+3] - mean) * rstd * gg.w + bb4.w);
        *(float4*)(out + c) = o4;
    }
}

// ---------------- TF32 mma.sync GEMM: CTA 128x128, 128 thr, warp 64x64, 4-stage ----------------
// A [M][K] row-major, B [K][N] row-major (pre-rounded to tf32).
// EPI: 0=bias; 1=bias+gelu+tf32r; 2=bias+window-reverse scatter+residual; 3=bias+residual
#define ASTR 20            // 16 + 4 pad
#define BSTR 136           // 128 + 8 pad
#define A_STAGE (128 * ASTR)
#define B_STAGE (16 * BSTR)
#define NSTAGE 4
#define GEMM_SMEM_BYTES (NSTAGE * (A_STAGE + B_STAGE) * 4)

template<int EPI>
__global__ __launch_bounds__(128, 2)
void tgemm(const float* __restrict__ A, const float* __restrict__ B,
           const float* __restrict__ bias, const float* __restrict__ R,
           float* __restrict__ Cc, int M, int N, int K) {
    extern __shared__ float sm[];
    float* As = sm;                          // [NSTAGE][128][ASTR]
    float* Bs = sm + NSTAGE * A_STAGE;       // [NSTAGE][16][BSTR]

    int tid = threadIdx.x, wid = tid >> 5, lane = tid & 31;
    int g = lane >> 2, c = lane & 3;
    int mw = (wid & 1) * 64, nw = (wid >> 1) * 64;
    int m0 = blockIdx.y * 128, n0 = blockIdx.x * 128;

    float acc[4][8][4];
    #pragma unroll
    for (int i = 0; i < 4; i++)
        #pragma unroll
        for (int j = 0; j < 8; j++)
            #pragma unroll
            for (int q = 0; q < 4; q++) acc[i][j][q] = 0.f;

    int arow = tid >> 1, achk = (tid & 1) * 8;   // 2 lanes per A row, 32B each
    int bkrow = tid >> 3, bseg = (tid & 7) * 16; // 8 lanes per B k-row, 64B each

    auto loadStage = [&](int t) {
        int st = t % NSTAGE;
        int k0 = t * 16;
        float* Ad = As + (size_t)st * A_STAGE;
        #pragma unroll
        for (int p = 0; p < 2; p++) {
            int r = arow + p * 64;
            int m = m0 + r;
            bool v = m < M;
            const float* src = v ? (A + (size_t)m * K + k0 + achk) : A;
            cp16(Ad + r * ASTR + achk,     src,           v ? 16 : 0);
            cp16(Ad + r * ASTR + achk + 4, v ? src + 4 : A, v ? 16 : 0);
        }
        float* Bd = Bs + (size_t)st * B_STAGE;
        const float* bsrc = B + (size_t)(k0 + bkrow) * N + n0 + bseg;
        #pragma unroll
        for (int i = 0; i < 4; i++)
            cp16(Bd + bkrow * BSTR + bseg + 4 * i, bsrc + 4 * i, 16);
        CP_COMMIT();
    };

    int nk = K / 16;
    #pragma unroll
    for (int t = 0; t < NSTAGE - 1; t++) loadStage(t);

    for (int t = 0; t < nk; t++) {
        asm volatile("cp.async.wait_group %0;" :: "n"(NSTAGE - 2) : "memory");
        __syncthreads();
        if (t + NSTAGE - 1 < nk) loadStage(t + NSTAGE - 1);
        else CP_COMMIT();
        const float* a_s = As + (size_t)(t % NSTAGE) * A_STAGE;
        const float* b_s = Bs + (size_t)(t % NSTAGE) * B_STAGE;
        #pragma unroll
        for (int kk = 0; kk < 2; kk++) {
            int kb = kk * 8;
            uint32_t af[4][4], bf[8][2];
            #pragma unroll
            for (int tm = 0; tm < 4; tm++) {
                const float* ap = a_s + (mw + tm * 16 + g) * ASTR + kb + c;
                af[tm][0] = __float_as_uint(ap[0]);
                af[tm][1] = __float_as_uint(ap[8 * ASTR]);
                af[tm][2] = __float_as_uint(ap[4]);
                af[tm][3] = __float_as_uint(ap[8 * ASTR + 4]);
            }
            #pragma unroll
            for (int tn = 0; tn < 8; tn++) {
                const float* bp = b_s + (kb + c) * BSTR + nw + tn * 8 + g;
                bf[tn][0] = __float_as_uint(bp[0]);
                bf[tn][1] = __float_as_uint(bp[4 * BSTR]);
            }
            #pragma unroll
            for (int tm = 0; tm < 4; tm++)
                #pragma unroll
                for (int tn = 0; tn < 8; tn++)
                    mma_tf32(acc[tm][tn], af[tm], bf[tn]);
        }
    }

    // epilogue
    #pragma unroll
    for (int tm = 0; tm < 4; tm++) {
        #pragma unroll
        for (int half = 0; half < 2; half++) {
            int m = m0 + mw + tm * 16 + g + half * 8;
            if (m >= M) continue;
            size_t obase = 0;
            const float* rbase = nullptr;
            bool valid = true;
            if (EPI == 2) {
                int bw = m / TOK, tt = m % TOK;
                int bb = bw / (NWH * NWW), rem = bw % (NWH * NWW);
                int wh = rem / NWW, ww = rem % NWW;
                int ii = tt / WS, jj = tt % WS;
                int h = wh * WS + ii, w = ww * WS + jj;
                if (h >= IMGH || w >= IMGW) valid = false;
                else { obase = ((size_t)(bb * IMGH + h) * IMGW + w) * CDIM; rbase = R + obase; }
            } else {
                obase = (size_t)m * N;
                if (EPI == 3) rbase = R + obase;
            }
            if (!valid) continue;
            #pragma unroll
            for (int tn = 0; tn < 8; tn++) {
                int n = n0 + nw + tn * 8 + 2 * c;
                float v0 = acc[tm][tn][half * 2 + 0] + bias[n];
                float v1 = acc[tm][tn][half * 2 + 1] + bias[n + 1];
                if (EPI == 1) {
                    v0 = tf32r(0.5f * v0 * (1.0f + erff(v0 * 0.7071067811865476f)));
                    v1 = tf32r(0.5f * v1 * (1.0f + erff(v1 * 0.7071067811865476f)));
                } else if (EPI == 2 || EPI == 3) {
                    v0 += rbase[n];
                    v1 += rbase[n + 1];
                }
                *(float2*)(Cc + obase + n) = make_float2(v0, v1);
            }
        }
    }
}

// ---------------- windowed attention ----------------
#define SM_QS   0
#define SM_VS   (TOK * 64)
#define SM_KS   (2 * TOK * 64)
#define SM_RH   (2 * TOK * 64 + TOK * 65)
#define SM_RW   (SM_RH + 27 * 65)
#define SM_PS   (SM_RW + 27 * 65)
#define SM_RHW  (SM_PS + 8 * 200)
#define SM_TOTAL_FLOATS (SM_RHW + 8 * 64)

__global__ void attn_kernel(const float* __restrict__ qkv,
                            const float* __restrict__ relh,
                            const float* __restrict__ relw,
                            float* __restrict__ attout) {
    extern __shared__ float smf[];
    float* qs = smf + SM_QS;
    float* vs = smf + SM_VS;
    float* ks = smf + SM_KS;
    float* Rh = smf + SM_RH;
    float* Rw = smf + SM_RW;
    float* Ps = smf + SM_PS;
    float* rhw = smf + SM_RHW;

    int blk = blockIdx.x;
    int bw = blk / NH, nh = blk % NH;
    int tid = threadIdx.x, lane = tid & 31, warp = tid >> 5;

    const float* base = qkv + (size_t)bw * TOK * QKVN + nh * HD;
    for (int t4 = tid; t4 < TOK * 16; t4 += 256) {
        int t = t4 >> 4, c4 = (t4 & 15) * 4;
        const float* p = base + (size_t)t * QKVN;
        float4 q4 = *(const float4*)(p + c4);
        float4 k4 = *(const float4*)(p + CDIM + c4);
        float4 v4 = *(const float4*)(p + 2 * CDIM + c4);
        *(float4*)(qs + t * 64 + c4) = q4;
        ks[t * 65 + c4 + 0] = k4.x;
        ks[t * 65 + c4 + 1] = k4.y;
        ks[t * 65 + c4 + 2] = k4.z;
        ks[t * 65 + c4 + 3] = k4.w;
        *(float4*)(vs + t * 64 + c4) = v4;
    }
    for (int idx = tid; idx < 27 * 64; idx += 256) {
        int rr = idx >> 6, c = idx & 63;
        Rh[rr * 65 + c] = relh[idx];
        Rw[rr * 65 + c] = relw[idx];
    }
    __syncthreads();

    const float scale = 0.125f;
    for (int qi = warp; qi < TOK; qi += 8) {
        int i = qi / WS, j = qi % WS;
        const float* qrow = qs + qi * 64;

        float rh = 0.f, rw = 0.f;
        if (lane < WS) {
            const float* rhrow = Rh + (i - lane + WS - 1) * 65;
            const float* rwrow = Rw + (j - lane + WS - 1) * 65;
            #pragma unroll 8
            for (int c = 0; c < 64; c++) {
                float qc = qrow[c];
                rh = fmaf(qc, rhrow[c], rh);
                rw = fmaf(qc, rwrow[c], rw);
            }
        }
        rhw[warp * 64 + lane] = rh;
        rhw[warp * 64 + 32 + lane] = rw;
        __syncwarp();

        float accv[7];
        #pragma unroll
        for (int m = 0; m < 7; m++) accv[m] = 0.f;
        #pragma unroll 4
        for (int c = 0; c < 64; c++) {
            float qc = qrow[c];
            #pragma unroll
            for (int m = 0; m < 7; m++) {
                int kj = lane + 32 * m;
                if (kj < TOK) accv[m] = fmaf(qc, ks[kj * 65 + c], accv[m]);
            }
        }
        float s[7];
        #pragma unroll
        for (int m = 0; m < 7; m++) {
            int kj = lane + 32 * m;
            if (kj < TOK) {
                int kk = kj / WS, ll = kj % WS;
                s[m] = accv[m] * scale + rhw[warp * 64 + kk] + rhw[warp * 64 + 32 + ll];
            } else {
                s[m] = -1e30f;
            }
        }
        float mx = -1e30f;
        #pragma unroll
        for (int m = 0; m < 7; m++) mx = fmaxf(mx, s[m]);
        #pragma unroll
        for (int o = 16; o > 0; o >>= 1) mx = fmaxf(mx, __shfl_xor_sync(0xffffffffu, mx, o));
        float p[7], sum = 0.f;
        #pragma unroll
        for (int m = 0; m < 7; m++) { p[m] = __expf(s[m] - mx); sum += p[m]; }
        #pragma unroll
        for (int o = 16; o > 0; o >>= 1) sum += __shfl_xor_sync(0xffffffffu, sum, o);
        float inv = __frcp_rn(sum);
        #pragma unroll
        for (int m = 0; m < 7; m++) {
            int kj = lane + 32 * m;
            if (kj < TOK) Ps[warp * 200 + kj] = p[m] * inv;
        }
        __syncwarp();

        float o0 = 0.f, o1 = 0.f;
        #pragma unroll 4
        for (int kj = 0; kj < TOK; kj++) {
            float pp = Ps[warp * 200 + kj];
            o0 = fmaf(pp, vs[kj * 64 + lane], o0);
            o1 = fmaf(pp, vs[kj * 64 + 32 + lane], o1);
        }
        float* orow = attout + ((size_t)(bw * TOK + qi)) * CDIM + nh * HD;
        orow[lane] = tf32r(o0);
        orow[lane + 32] = tf32r(o1);
        __syncwarp();
    }
}

// ---------------- launch ----------------
extern "C" void kernel_launch(void* const* d_in, const int* in_sizes, int n_in,
                              void* d_out, int out_size) {
    const float* x       = (const float*)d_in[0];
    const float* ln1_g   = (const float*)d_in[1];
    const float* ln1_b   = (const float*)d_in[2];
    const float* w_qkv   = (const float*)d_in[3];
    const float* b_qkv   = (const float*)d_in[4];
    const float* w_proj  = (const float*)d_in[5];
    const float* b_proj  = (const float*)d_in[6];
    const float* relh    = (const float*)d_in[7];
    const float* relw    = (const float*)d_in[8];
    const float* ln2_g   = (const float*)d_in[9];
    const float* ln2_b   = (const float*)d_in[10];
    const float* w_fc1   = (const float*)d_in[11];
    const float* b_fc1   = (const float*)d_in[12];
    const float* w_fc2   = (const float*)d_in[13];
    const float* b_fc2   = (const float*)d_in[14];
    float* out = (float*)d_out;

    float *win, *qkv, *att, *x2, *yln, *y1, *wqkv, *wproj, *wfc1, *wfc2;
    cudaGetSymbolAddress((void**)&win, g_win);
    cudaGetSymbolAddress((void**)&qkv, g_qkv);
    cudaGetSymbolAddress((void**)&att, g_att);
    cudaGetSymbolAddress((void**)&x2,  g_x2);
    cudaGetSymbolAddress((void**)&yln, g_yln);
    cudaGetSymbolAddress((void**)&y1,  g_y1);
    cudaGetSymbolAddress((void**)&wqkv,  g_wqkv);
    cudaGetSymbolAddress((void**)&wproj, g_wproj);
    cudaGetSymbolAddress((void**)&wfc1,  g_wfc1);
    cudaGetSymbolAddress((void**)&wfc2,  g_wfc2);

    const int smem_attn = SM_TOTAL_FLOATS * 4;
    cudaFuncSetAttribute(attn_kernel, cudaFuncAttributeMaxDynamicSharedMemorySize, smem_attn);
    cudaFuncSetAttribute(tgemm<0>, cudaFuncAttributeMaxDynamicSharedMemorySize, GEMM_SMEM_BYTES);
    cudaFuncSetAttribute(tgemm<1>, cudaFuncAttributeMaxDynamicSharedMemorySize, GEMM_SMEM_BYTES);
    cudaFuncSetAttribute(tgemm<2>, cudaFuncAttributeMaxDynamicSharedMemorySize, GEMM_SMEM_BYTES);
    cudaFuncSetAttribute(tgemm<3>, cudaFuncAttributeMaxDynamicSharedMemorySize, GEMM_SMEM_BYTES);

    // round weights to tf32
    round_tf32_kernel<<<(CDIM * QKVN / 4 + 255) / 256, 256>>>(w_qkv, wqkv, CDIM * QKVN / 4);
    round_tf32_kernel<<<(CDIM * CDIM / 4 + 255) / 256, 256>>>(w_proj, wproj, CDIM * CDIM / 4);
    round_tf32_kernel<<<(CDIM * FFN / 4 + 255) / 256, 256>>>(w_fc1, wfc1, CDIM * FFN / 4);
    round_tf32_kernel<<<(FFN * CDIM / 4 + 255) / 256, 256>>>(w_fc2, wfc2, FFN * CDIM / 4);

    // 1) LN1 + window partition
    ln1_win_kernel<<<(ROWS_WIN * 32 + 255) / 256, 256>>>(x, ln1_g, ln1_b, win);

    // 2) QKV GEMM [19600,768]x[768,2304]
    tgemm<0><<<dim3(QKVN / 128, (ROWS_WIN + 127) / 128), 128, GEMM_SMEM_BYTES>>>(
        win, wqkv, b_qkv, nullptr, qkv, ROWS_WIN, QKVN, CDIM);

    // 3) attention
    attn_kernel<<<BW * NH, 256, smem_attn>>>(qkv, relh, relw, att);

    // 4) proj + window reverse + residual
    tgemm<2><<<dim3(CDIM / 128, (ROWS_WIN + 127) / 128), 128, GEMM_SMEM_BYTES>>>(
        att, wproj, b_proj, x, x2, ROWS_WIN, CDIM, CDIM);

    // 5) LN2
    ln2_kernel<<<(ROWS_IMG * 32 + 255) / 256, 256>>>(x2, ln2_g, ln2_b, yln);

    // 6) fc1 + gelu
    tgemm<1><<<dim3(FFN / 128, ROWS_IMG / 128), 128, GEMM_SMEM_BYTES>>>(
        yln, wfc1, b_fc1, nullptr, y1, ROWS_IMG, FFN, CDIM);

    // 7) fc2 + residual
    tgemm<3><<<dim3(CDIM / 128, ROWS_IMG / 128), 128, GEMM_SMEM_BYTES>>>(
        y1, wfc2, b_fc2, x2, out, ROWS_IMG, CDIM, FFN);
}

// round 6
// speedup vs baseline: 1.1150x; 1.0579x over previous
#include <cuda_runtime.h>
#include <math.h>
#include <stdint.h>

// ---------------- problem constants ----------------
#define BATCH 4
#define IMGH  64
#define IMGW  64
#define CDIM  768
#define WS    14
#define TOK   196
#define NH    12
#define HD    64
#define NWH   5
#define NWW   5
#define BW    100
#define ROWS_WIN 19600
#define ROWS_IMG 16384
#define QKVN  2304
#define FFN   3072

// ---------------- scratch ----------------
__device__ float g_win[(size_t)ROWS_WIN * CDIM];
__device__ float g_qkv[(size_t)ROWS_WIN * QKVN];
__device__ float g_att[(size_t)ROWS_WIN * CDIM];
__device__ float g_x2 [(size_t)ROWS_IMG * CDIM];
__device__ float g_yln[(size_t)ROWS_IMG * CDIM];
__device__ float g_y1 [(size_t)ROWS_IMG * FFN];
__device__ float g_wqkv[(size_t)CDIM * QKVN];
__device__ float g_wproj[(size_t)CDIM * CDIM];
__device__ float g_wfc1[(size_t)CDIM * FFN];
__device__ float g_wfc2[(size_t)FFN * CDIM];

// ---------------- helpers ----------------
__device__ __forceinline__ float tf32r(float x) {
    uint32_t u;
    asm("cvt.rna.tf32.f32 %0, %1;" : "=r"(u) : "f"(x));
    return __uint_as_float(u);
}
__device__ __forceinline__ uint32_t smem_u32(const void* p) {
    uint32_t a;
    asm("{ .reg .u64 t; cvta.to.shared.u64 t, %1; cvt.u32.u64 %0, t; }" : "=r"(a) : "l"(p));
    return a;
}
__device__ __forceinline__ void cp16(void* sdst, const void* gsrc, int bytes) {
    uint32_t sa = smem_u32(sdst);
    asm volatile("cp.async.cg.shared.global [%0], [%1], 16, %2;" :: "r"(sa), "l"(gsrc), "r"(bytes));
}
#define CP_COMMIT() asm volatile("cp.async.commit_group;")

__device__ __forceinline__ void mma_tf32(float c[4], const uint32_t a[4], const uint32_t b[2]) {
    asm volatile(
        "mma.sync.aligned.m16n8k8.row.col.f32.tf32.tf32.f32 "
        "{%0,%1,%2,%3}, {%4,%5,%6,%7}, {%8,%9}, {%0,%1,%2,%3};"
        : "+f"(c[0]), "+f"(c[1]), "+f"(c[2]), "+f"(c[3])
        : "r"(a[0]), "r"(a[1]), "r"(a[2]), "r"(a[3]), "r"(b[0]), "r"(b[1]));
}

// ---------------- weight tf32 rounding ----------------
__global__ void round_tf32_kernel(const float* __restrict__ in, float* __restrict__ out, int n4) {
    int i = blockIdx.x * blockDim.x + threadIdx.x;
    if (i >= n4) return;
    float4 f = ((const float4*)in)[i];
    f.x = tf32r(f.x); f.y = tf32r(f.y); f.z = tf32r(f.z); f.w = tf32r(f.w);
    ((float4*)out)[i] = f;
}

// ---------------- LN1 + window partition ----------------
__global__ void ln1_win_kernel(const float* __restrict__ x,
                               const float* __restrict__ g,
                               const float* __restrict__ b,
                               float* __restrict__ out_) {
    int warp = (blockIdx.x * blockDim.x + threadIdx.x) >> 5;
    int lane = threadIdx.x & 31;
    if (warp >= ROWS_WIN) return;
    int r = warp;
    int bw = r / TOK, t = r % TOK;
    int bb = bw / (NWH * NWW), rem = bw % (NWH * NWW);
    int wh = rem / NWW, ww = rem % NWW;
    int i = t / WS, j = t % WS;
    int h = wh * WS + i, w = ww * WS + j;
    float* out = out_ + (size_t)r * CDIM;
    if (h >= IMGH || w >= IMGW) {
        float4 z = make_float4(0.f, 0.f, 0.f, 0.f);
        #pragma unroll
        for (int q = 0; q < 6; q++) *(float4*)(out + lane * 4 + q * 128) = z;
        return;
    }
    const float* row = x + ((size_t)(bb * IMGH + h) * IMGW + w) * CDIM;
    float v[24];
    float s = 0.f;
    #pragma unroll
    for (int q = 0; q < 6; q++) {
        float4 f = *(const float4*)(row + lane * 4 + q * 128);
        v[q*4+0] = f.x; v[q*4+1] = f.y; v[q*4+2] = f.z; v[q*4+3] = f.w;
        s += f.x + f.y + f.z + f.w;
    }
    #pragma unroll
    for (int o = 16; o > 0; o >>= 1) s += __shfl_xor_sync(0xffffffffu, s, o);
    float mean = s * (1.0f / CDIM);
    float ss = 0.f;
    #pragma unroll
    for (int q = 0; q < 24; q++) { float d = v[q] - mean; ss += d * d; }
    #pragma unroll
    for (int o = 16; o > 0; o >>= 1) ss += __shfl_xor_sync(0xffffffffu, ss, o);
    float rstd = rsqrtf(ss * (1.0f / CDIM) + 1e-6f);
    #pragma unroll
    for (int q = 0; q < 6; q++) {
        int c = lane * 4 + q * 128;
        float4 gg = *(const float4*)(g + c);
        float4 bb4 = *(const float4*)(b + c);
        float4 o4;
        o4.x = tf32r((v[q*4+0] - mean) * rstd * gg.x + bb4.x);
        o4.y = tf32r((v[q*4+1] - mean) * rstd * gg.y + bb4.y);
        o4.z = tf32r((v[q*4+2] - mean) * rstd * gg.z + bb4.z);
        o4.w = tf32r((v[q*4+3] - mean) * rstd * gg.w + bb4.w);
        *(float4*)(out + c) = o4;
    }
}

// ---------------- LN2 ----------------
__global__ void ln2_kernel(const float* __restrict__ x,
                           const float* __restrict__ g,
                           const float* __restrict__ b,
                           float* __restrict__ out_) {
    int warp = (blockIdx.x * blockDim.x + threadIdx.x) >> 5;
    int lane = threadIdx.x & 31;
    if (warp >= ROWS_IMG) return;
    const float* row = x + (size_t)warp * CDIM;
    float* out = out_ + (size_t)warp * CDIM;
    float v[24];
    float s = 0.f;
    #pragma unroll
    for (int q = 0; q < 6; q++) {
        float4 f = *(const float4*)(row + lane * 4 + q * 128);
        v[q*4+0] = f.x; v[q*4+1] = f.y; v[q*4+2] = f.z; v[q*4+3] = f.w;
        s += f.x + f.y + f.z + f.w;
    }
    #pragma unroll
    for (int o = 16; o > 0; o >>= 1) s += __shfl_xor_sync(0xffffffffu, s, o);
    float mean = s * (1.0f / CDIM);
    float ss = 0.f;
    #pragma unroll
    for (int q = 0; q < 24; q++) { float d = v[q] - mean; ss += d * d; }
    #pragma unroll
    for (int o = 16; o > 0; o >>= 1) ss += __shfl_xor_sync(0xffffffffu, ss, o);
    float rstd = rsqrtf(ss * (1.0f / CDIM) + 1e-6f);
    #pragma unroll
    for (int q = 0; q < 6; q++) {
        int c = lane * 4 + q * 128;
        float4 gg = *(const float4*)(g + c);
        float4 bb4 = *(const float4*)(b + c);
        float4 o4;
        o4.x = tf32r((v[q*4+0] - mean) * rstd * gg.x + bb4.x);
        o4.y = tf32r((v[q*4+1] - mean) * rstd * gg.y + bb4.y);
        o4.z = tf32r((v[q*4+2] - mean) * rstd * gg.z + bb4.z);
        o4.w = tf32r((v[q*4+3] - mean) * rstd * gg.w + bb4.w);
        *(float4*)(out + c) = o4;
    }
}

// ---------------- TF32 mma.sync GEMM ----------------
// CTA 128x128, 256 threads, 8 warps (2M x 4N), warp tile 64x32, 5-stage cp.async (k-slab 16).
// A [M][K] row-major, B [K][N] row-major (pre-rounded tf32).
// EPI: 0=bias; 1=bias+gelu+tf32r; 2=bias+window-reverse scatter+residual; 3=bias+residual
#define ASTR 20            // 16 + 4 pad
#define BSTR 136           // 128 + 8 pad
#define A_STAGE (128 * ASTR)
#define B_STAGE (16 * BSTR)
#define NSTAGE 5
#define GEMM_SMEM_BYTES (NSTAGE * (A_STAGE + B_STAGE) * 4)

template<int EPI>
__global__ __launch_bounds__(256, 2)
void tgemm(const float* __restrict__ A, const float* __restrict__ B,
           const float* __restrict__ bias, const float* __restrict__ R,
           float* __restrict__ Cc, int M, int N, int K) {
    extern __shared__ float sm[];
    float* As = sm;                          // [NSTAGE][128][ASTR]
    float* Bs = sm + NSTAGE * A_STAGE;       // [NSTAGE][16][BSTR]

    int tid = threadIdx.x, wid = tid >> 5, lane = tid & 31;
    int g = lane >> 2, c = lane & 3;
    int mw = (wid >> 2) * 64, nw = (wid & 3) * 32;
    int m0 = blockIdx.y * 128, n0 = blockIdx.x * 128;

    float acc[4][4][4];
    #pragma unroll
    for (int i = 0; i < 4; i++)
        #pragma unroll
        for (int j = 0; j < 4; j++)
            #pragma unroll
            for (int q = 0; q < 4; q++) acc[i][j][q] = 0.f;

    int arow = tid >> 1, achk = (tid & 1) * 8;    // 2 lanes/A-row, 32B each
    int bkrow = tid >> 4, bseg = (tid & 15) * 8;  // 16 lanes/B-krow, 32B each

    auto loadStage = [&](int t) {
        int st = t % NSTAGE;
        int k0 = t * 16;
        float* Ad = As + (size_t)st * A_STAGE;
        int m = m0 + arow;
        bool v = m < M;
        const float* src = v ? (A + (size_t)m * K + k0 + achk) : A;
        cp16(Ad + arow * ASTR + achk,     src,             v ? 16 : 0);
        cp16(Ad + arow * ASTR + achk + 4, v ? src + 4 : A, v ? 16 : 0);
        float* Bd = Bs + (size_t)st * B_STAGE;
        const float* bsrc = B + (size_t)(k0 + bkrow) * N + n0 + bseg;
        cp16(Bd + bkrow * BSTR + bseg,     bsrc,     16);
        cp16(Bd + bkrow * BSTR + bseg + 4, bsrc + 4, 16);
        CP_COMMIT();
    };

    int nk = K / 16;
    #pragma unroll
    for (int t = 0; t < NSTAGE - 1; t++) loadStage(t);

    for (int t = 0; t < nk; t++) {
        asm volatile("cp.async.wait_group %0;" :: "n"(NSTAGE - 2) : "memory");
        __syncthreads();
        if (t + NSTAGE - 1 < nk) loadStage(t + NSTAGE - 1);
        else CP_COMMIT();
        const float* a_s = As + (size_t)(t % NSTAGE) * A_STAGE;
        const float* b_s = Bs + (size_t)(t % NSTAGE) * B_STAGE;
        #pragma unroll
        for (int kk = 0; kk < 2; kk++) {
            int kb = kk * 8;
            uint32_t af[4][4], bf[4][2];
            #pragma unroll
            for (int tm = 0; tm < 4; tm++) {
                const float* ap = a_s + (mw + tm * 16 + g) * ASTR + kb + c;
                af[tm][0] = __float_as_uint(ap[0]);
                af[tm][1] = __float_as_uint(ap[8 * ASTR]);
                af[tm][2] = __float_as_uint(ap[4]);
                af[tm][3] = __float_as_uint(ap[8 * ASTR + 4]);
            }
            #pragma unroll
            for (int tn = 0; tn < 4; tn++) {
                const float* bp = b_s + (kb + c) * BSTR + nw + tn * 8 + g;
                bf[tn][0] = __float_as_uint(bp[0]);
                bf[tn][1] = __float_as_uint(bp[4 * BSTR]);
            }
            #pragma unroll
            for (int tm = 0; tm < 4; tm++)
                #pragma unroll
                for (int tn = 0; tn < 4; tn++)
                    mma_tf32(acc[tm][tn], af[tm], bf[tn]);
        }
        __syncthreads();
    }

    // epilogue
    #pragma unroll
    for (int tm = 0; tm < 4; tm++) {
        #pragma unroll
        for (int half = 0; half < 2; half++) {
            int m = m0 + mw + tm * 16 + g + half * 8;
            if (m >= M) continue;
            size_t obase = 0;
            const float* rbase = nullptr;
            bool valid = true;
            if (EPI == 2) {
                int bw = m / TOK, tt = m % TOK;
                int bb = bw / (NWH * NWW), rem = bw % (NWH * NWW);
                int wh = rem / NWW, ww = rem % NWW;
                int ii = tt / WS, jj = tt % WS;
                int h = wh * WS + ii, w = ww * WS + jj;
                if (h >= IMGH || w >= IMGW) valid = false;
                else { obase = ((size_t)(bb * IMGH + h) * IMGW + w) * CDIM; rbase = R + obase; }
            } else {
                obase = (size_t)m * N;
                if (EPI == 3) rbase = R + obase;
            }
            if (!valid) continue;
            #pragma unroll
            for (int tn = 0; tn < 4; tn++) {
                int n = n0 + nw + tn * 8 + 2 * c;
                float v0 = acc[tm][tn][half * 2 + 0] + bias[n];
                float v1 = acc[tm][tn][half * 2 + 1] + bias[n + 1];
                if (EPI == 1) {
                    v0 = tf32r(0.5f * v0 * (1.0f + erff(v0 * 0.7071067811865476f)));
                    v1 = tf32r(0.5f * v1 * (1.0f + erff(v1 * 0.7071067811865476f)));
                } else if (EPI == 2 || EPI == 3) {
                    v0 += rbase[n];
                    v1 += rbase[n + 1];
                }
                *(float2*)(Cc + obase + n) = make_float2(v0, v1);
            }
        }
    }
}

// ---------------- windowed attention ----------------
#define SM_QS   0
#define SM_VS   (TOK * 64)
#define SM_KS   (2 * TOK * 64)
#define SM_RH   (2 * TOK * 64 + TOK * 65)
#define SM_RW   (SM_RH + 27 * 65)
#define SM_PS   (SM_RW + 27 * 65)
#define SM_RHW  (SM_PS + 8 * 200)
#define SM_TOTAL_FLOATS (SM_RHW + 8 * 64)

__global__ void attn_kernel(const float* __restrict__ qkv,
                            const float* __restrict__ relh,
                            const float* __restrict__ relw,
                            float* __restrict__ attout) {
    extern __shared__ float smf[];
    float* qs = smf + SM_QS;
    float* vs = smf + SM_VS;
    float* ks = smf + SM_KS;
    float* Rh = smf + SM_RH;
    float* Rw = smf + SM_RW;
    float* Ps = smf + SM_PS;
    float* rhw = smf + SM_RHW;

    int blk = blockIdx.x;
    int bw = blk / NH, nh = blk % NH;
    int tid = threadIdx.x, lane = tid & 31, warp = tid >> 5;

    const float* base = qkv + (size_t)bw * TOK * QKVN + nh * HD;
    for (int t4 = tid; t4 < TOK * 16; t4 += 256) {
        int t = t4 >> 4, c4 = (t4 & 15) * 4;
        const float* p = base + (size_t)t * QKVN;
        float4 q4 = *(const float4*)(p + c4);
        float4 k4 = *(const float4*)(p + CDIM + c4);
        float4 v4 = *(const float4*)(p + 2 * CDIM + c4);
        *(float4*)(qs + t * 64 + c4) = q4;
        ks[t * 65 + c4 + 0] = k4.x;
        ks[t * 65 + c4 + 1] = k4.y;
        ks[t * 65 + c4 + 2] = k4.z;
        ks[t * 65 + c4 + 3] = k4.w;
        *(float4*)(vs + t * 64 + c4) = v4;
    }
    for (int idx = tid; idx < 27 * 64; idx += 256) {
        int rr = idx >> 6, c = idx & 63;
        Rh[rr * 65 + c] = relh[idx];
        Rw[rr * 65 + c] = relw[idx];
    }
    __syncthreads();

    const float scale = 0.125f;
    for (int qi = warp; qi < TOK; qi += 8) {
        int i = qi / WS, j = qi % WS;
        const float* qrow = qs + qi * 64;

        float rh = 0.f, rw = 0.f;
        if (lane < WS) {
            const float* rhrow = Rh + (i - lane + WS - 1) * 65;
            const float* rwrow = Rw + (j - lane + WS - 1) * 65;
            #pragma unroll 8
            for (int c = 0; c < 64; c++) {
                float qc = qrow[c];
                rh = fmaf(qc, rhrow[c], rh);
                rw = fmaf(qc, rwrow[c], rw);
            }
        }
        rhw[warp * 64 + lane] = rh;
        rhw[warp * 64 + 32 + lane] = rw;
        __syncwarp();

        float accv[7];
        #pragma unroll
        for (int m = 0; m < 7; m++) accv[m] = 0.f;
        #pragma unroll 4
        for (int c = 0; c < 64; c++) {
            float qc = qrow[c];
            #pragma unroll
            for (int m = 0; m < 7; m++) {
                int kj = lane + 32 * m;
                if (kj < TOK) accv[m] = fmaf(qc, ks[kj * 65 + c], accv[m]);
            }
        }
        float s[7];
        #pragma unroll
        for (int m = 0; m < 7; m++) {
            int kj = lane + 32 * m;
            if (kj < TOK) {
                int kk = kj / WS, ll = kj % WS;
                s[m] = accv[m] * scale + rhw[warp * 64 + kk] + rhw[warp * 64 + 32 + ll];
            } else {
                s[m] = -1e30f;
            }
        }
        float mx = -1e30f;
        #pragma unroll
        for (int m = 0; m < 7; m++) mx = fmaxf(mx, s[m]);
        #pragma unroll
        for (int o = 16; o > 0; o >>= 1) mx = fmaxf(mx, __shfl_xor_sync(0xffffffffu, mx, o));
        float p[7], sum = 0.f;
        #pragma unroll
        for (int m = 0; m < 7; m++) { p[m] = __expf(s[m] - mx); sum += p[m]; }
        #pragma unroll
        for (int o = 16; o > 0; o >>= 1) sum += __shfl_xor_sync(0xffffffffu, sum, o);
        float inv = __frcp_rn(sum);
        #pragma unroll
        for (int m = 0; m < 7; m++) {
            int kj = lane + 32 * m;
            if (kj < TOK) Ps[warp * 200 + kj] = p[m] * inv;
        }
        __syncwarp();

        float o0 = 0.f, o1 = 0.f;
        #pragma unroll 4
        for (int kj = 0; kj < TOK; kj++) {
            float pp = Ps[warp * 200 + kj];
            o0 = fmaf(pp, vs[kj * 64 + lane], o0);
            o1 = fmaf(pp, vs[kj * 64 + 32 + lane], o1);
        }
        float* orow = attout + ((size_t)(bw * TOK + qi)) * CDIM + nh * HD;
        orow[lane] = tf32r(o0);
        orow[lane + 32] = tf32r(o1);
        __syncwarp();
    }
}

// ---------------- launch ----------------
extern "C" void kernel_launch(void* const* d_in, const int* in_sizes, int n_in,
                              void* d_out, int out_size) {
    const float* x       = (const float*)d_in[0];
    const float* ln1_g   = (const float*)d_in[1];
    const float* ln1_b   = (const float*)d_in[2];
    const float* w_qkv   = (const float*)d_in[3];
    const float* b_qkv   = (const float*)d_in[4];
    const float* w_proj  = (const float*)d_in[5];
    const float* b_proj  = (const float*)d_in[6];
    const float* relh    = (const float*)d_in[7];
    const float* relw    = (const float*)d_in[8];
    const float* ln2_g   = (const float*)d_in[9];
    const float* ln2_b   = (const float*)d_in[10];
    const float* w_fc1   = (const float*)d_in[11];
    const float* b_fc1   = (const float*)d_in[12];
    const float* w_fc2   = (const float*)d_in[13];
    const float* b_fc2   = (const float*)d_in[14];
    float* out = (float*)d_out;

    float *win, *qkv, *att, *x2, *yln, *y1, *wqkv, *wproj, *wfc1, *wfc2;
    cudaGetSymbolAddress((void**)&win, g_win);
    cudaGetSymbolAddress((void**)&qkv, g_qkv);
    cudaGetSymbolAddress((void**)&att, g_att);
    cudaGetSymbolAddress((void**)&x2,  g_x2);
    cudaGetSymbolAddress((void**)&yln, g_yln);
    cudaGetSymbolAddress((void**)&y1,  g_y1);
    cudaGetSymbolAddress((void**)&wqkv,  g_wqkv);
    cudaGetSymbolAddress((void**)&wproj, g_wproj);
    cudaGetSymbolAddress((void**)&wfc1,  g_wfc1);
    cudaGetSymbolAddress((void**)&wfc2,  g_wfc2);

    const int smem_attn = SM_TOTAL_FLOATS * 4;
    cudaFuncSetAttribute(attn_kernel, cudaFuncAttributeMaxDynamicSharedMemorySize, smem_attn);
    cudaFuncSetAttribute(tgemm<0>, cudaFuncAttributeMaxDynamicSharedMemorySize, GEMM_SMEM_BYTES);
    cudaFuncSetAttribute(tgemm<1>, cudaFuncAttributeMaxDynamicSharedMemorySize, GEMM_SMEM_BYTES);
    cudaFuncSetAttribute(tgemm<2>, cudaFuncAttributeMaxDynamicSharedMemorySize, GEMM_SMEM_BYTES);
    cudaFuncSetAttribute(tgemm<3>, cudaFuncAttributeMaxDynamicSharedMemorySize, GEMM_SMEM_BYTES);

    // 1) LN1 + window partition FIRST (so ncu -s 5 captures the qkv GEMM next)
    ln1_win_kernel<<<(ROWS_WIN * 32 + 255) / 256, 256>>>(x, ln1_g, ln1_b, win);

    // round weights to tf32
    round_tf32_kernel<<<(CDIM * QKVN / 4 + 255) / 256, 256>>>(w_qkv, wqkv, CDIM * QKVN / 4);
    round_tf32_kernel<<<(CDIM * CDIM / 4 + 255) / 256, 256>>>(w_proj, wproj, CDIM * CDIM / 4);
    round_tf32_kernel<<<(CDIM * FFN / 4 + 255) / 256, 256>>>(w_fc1, wfc1, CDIM * FFN / 4);
    round_tf32_kernel<<<(FFN * CDIM / 4 + 255) / 256, 256>>>(w_fc2, wfc2, FFN * CDIM / 4);

    // 2) QKV GEMM [19600,768]x[768,2304]  (6th launch -> ncu capture target)
    tgemm<0><<<dim3(QKVN / 128, (ROWS_WIN + 127) / 128), 256, GEMM_SMEM_BYTES>>>(
        win, wqkv, b_qkv, nullptr, qkv, ROWS_WIN, QKVN, CDIM);

    // 3) attention
    attn_kernel<<<BW * NH, 256, smem_attn>>>(qkv, relh, relw, att);

    // 4) proj + window reverse + residual
    tgemm<2><<<dim3(CDIM / 128, (ROWS_WIN + 127) / 128), 256, GEMM_SMEM_BYTES>>>(
        att, wproj, b_proj, x, x2, ROWS_WIN, CDIM, CDIM);

    // 5) LN2
    ln2_kernel<<<(ROWS_IMG * 32 + 255) / 256, 256>>>(x2, ln2_g, ln2_b, yln);

    // 6) fc1 + gelu
    tgemm<1><<<dim3(FFN / 128, ROWS_IMG / 128), 256, GEMM_SMEM_BYTES>>>(
        yln, wfc1, b_fc1, nullptr, y1, ROWS_IMG, FFN, CDIM);

    // 7) fc2 + residual
    tgemm<3><<<dim3(CDIM / 128, ROWS_IMG / 128), 256, GEMM_SMEM_BYTES>>>(
        y1, wfc2, b_fc2, x2, out, ROWS_IMG, CDIM, FFN);
}

// round 7
// speedup vs baseline: 1.5436x; 1.3843x over previous
#include <cuda_runtime.h>
#include <cuda_fp16.h>
#include <math.h>
#include <stdint.h>

// ---------------- problem constants ----------------
#define BATCH 4
#define IMGH  64
#define IMGW  64
#define CDIM  768
#define WS    14
#define TOK   196
#define NH    12
#define HD    64
#define NWH   5
#define NWW   5
#define BW    100
#define ROWS_WIN 19600
#define ROWS_IMG 16384
#define QKVN  2304
#define FFN   3072

// ---------------- scratch ----------------
__device__ __half g_win[(size_t)ROWS_WIN * CDIM];
__device__ __half g_qkv[(size_t)ROWS_WIN * QKVN];
__device__ __half g_att[(size_t)ROWS_WIN * CDIM];
__device__ float  g_x2 [(size_t)ROWS_IMG * CDIM];
__device__ __half g_yln[(size_t)ROWS_IMG * CDIM];
__device__ __half g_y1 [(size_t)ROWS_IMG * FFN];
__device__ __half g_wqkv[(size_t)CDIM * QKVN];   // interleaved [K/2][N] half2
__device__ __half g_wproj[(size_t)CDIM * CDIM];
__device__ __half g_wfc1[(size_t)CDIM * FFN];
__device__ __half g_wfc2[(size_t)FFN * CDIM];

// ---------------- helpers ----------------
__device__ __forceinline__ uint32_t smem_u32(const void* p) {
    uint32_t a;
    asm("{ .reg .u64 t; cvta.to.shared.u64 t, %1; cvt.u32.u64 %0, t; }" : "=r"(a) : "l"(p));
    return a;
}
__device__ __forceinline__ void cp16(void* sdst, const void* gsrc, int bytes) {
    uint32_t sa = smem_u32(sdst);
    asm volatile("cp.async.cg.shared.global [%0], [%1], 16, %2;" :: "r"(sa), "l"(gsrc), "r"(bytes));
}
#define CP_COMMIT() asm volatile("cp.async.commit_group;")

__device__ __forceinline__ void mma_f16(float c[4], const uint32_t a[4], const uint32_t b[2]) {
    asm volatile(
        "mma.sync.aligned.m16n8k16.row.col.f32.f16.f16.f32 "
        "{%0,%1,%2,%3}, {%4,%5,%6,%7}, {%8,%9}, {%0,%1,%2,%3};"
        : "+f"(c[0]), "+f"(c[1]), "+f"(c[2]), "+f"(c[3])
        : "r"(a[0]), "r"(a[1]), "r"(a[2]), "r"(a[3]), "r"(b[0]), "r"(b[1]));
}

__device__ __forceinline__ float4 h4tof4(const __half* p) {
    __half2 h0 = *(const __half2*)p;
    __half2 h1 = *(const __half2*)(p + 2);
    float2 a = __half22float2(h0), b = __half22float2(h1);
    return make_float4(a.x, a.y, b.x, b.y);
}

// ---------------- weight fp32 -> half2 k-pair interleave: in[K][N] -> out2[K/2][N] ----------------
__global__ void w2h_kernel(const float* __restrict__ in, __half* __restrict__ out, int Kd, int Nd) {
    int idx = blockIdx.x * blockDim.x + threadIdx.x;
    int tot = (Kd / 2) * Nd;
    if (idx >= tot) return;
    int kp = idx / Nd, n = idx % Nd;
    float a = in[(size_t)(2 * kp) * Nd + n];
    float b = in[(size_t)(2 * kp + 1) * Nd + n];
    ((__half2*)out)[idx] = __floats2half2_rn(a, b);
}

// ---------------- LN1 + window partition -> half ----------------
__global__ void ln1_win_kernel(const float* __restrict__ x,
                               const float* __restrict__ g,
                               const float* __restrict__ b,
                               __half* __restrict__ out_) {
    int warp = (blockIdx.x * blockDim.x + threadIdx.x) >> 5;
    int lane = threadIdx.x & 31;
    if (warp >= ROWS_WIN) return;
    int r = warp;
    int bw = r / TOK, t = r % TOK;
    int bb = bw / (NWH * NWW), rem = bw % (NWH * NWW);
    int wh = rem / NWW, ww = rem % NWW;
    int i = t / WS, j = t % WS;
    int h = wh * WS + i, w = ww * WS + j;
    __half* out = out_ + (size_t)r * CDIM;
    if (h >= IMGH || w >= IMGW) {
        uint2 z = make_uint2(0u, 0u);
        #pragma unroll
        for (int q = 0; q < 6; q++) *(uint2*)(out + lane * 4 + q * 128) = z;
        return;
    }
    const float* row = x + ((size_t)(bb * IMGH + h) * IMGW + w) * CDIM;
    float v[24];
    float s = 0.f;
    #pragma unroll
    for (int q = 0; q < 6; q++) {
        float4 f = *(const float4*)(row + lane * 4 + q * 128);
        v[q*4+0] = f.x; v[q*4+1] = f.y; v[q*4+2] = f.z; v[q*4+3] = f.w;
        s += f.x + f.y + f.z + f.w;
    }
    #pragma unroll
    for (int o = 16; o > 0; o >>= 1) s += __shfl_xor_sync(0xffffffffu, s, o);
    float mean = s * (1.0f / CDIM);
    float ss = 0.f;
    #pragma unroll
    for (int q = 0; q < 24; q++) { float d = v[q] - mean; ss += d * d; }
    #pragma unroll
    for (int o = 16; o > 0; o >>= 1) ss += __shfl_xor_sync(0xffffffffu, ss, o);
    float rstd = rsqrtf(ss * (1.0f / CDIM) + 1e-6f);
    #pragma unroll
    for (int q = 0; q < 6; q++) {
        int c = lane * 4 + q * 128;
        float4 gg = *(const float4*)(g + c);
        float4 bb4 = *(const float4*)(b + c);
        __half2 h0 = __floats2half2_rn((v[q*4+0] - mean) * rstd * gg.x + bb4.x,
                                       (v[q*4+1] - mean) * rstd * gg.y + bb4.y);
        __half2 h1 = __floats2half2_rn((v[q*4+2] - mean) * rstd * gg.z + bb4.z,
                                       (v[q*4+3] - mean) * rstd * gg.w + bb4.w);
        *(__half2*)(out + c) = h0;
        *(__half2*)(out + c + 2) = h1;
    }
}

// ---------------- LN2 -> half ----------------
__global__ void ln2_kernel(const float* __restrict__ x,
                           const float* __restrict__ g,
                           const float* __restrict__ b,
                           __half* __restrict__ out_) {
    int warp = (blockIdx.x * blockDim.x + threadIdx.x) >> 5;
    int lane = threadIdx.x & 31;
    if (warp >= ROWS_IMG) return;
    const float* row = x + (size_t)warp * CDIM;
    __half* out = out_ + (size_t)warp * CDIM;
    float v[24];
    float s = 0.f;
    #pragma unroll
    for (int q = 0; q < 6; q++) {
        float4 f = *(const float4*)(row + lane * 4 + q * 128);
        v[q*4+0] = f.x; v[q*4+1] = f.y; v[q*4+2] = f.z; v[q*4+3] = f.w;
        s += f.x + f.y + f.z + f.w;
    }
    #pragma unroll
    for (int o = 16; o > 0; o >>= 1) s += __shfl_xor_sync(0xffffffffu, s, o);
    float mean = s * (1.0f / CDIM);
    float ss = 0.f;
    #pragma unroll
    for (int q = 0; q < 24; q++) { float d = v[q] - mean; ss += d * d; }
    #pragma unroll
    for (int o = 16; o > 0; o >>= 1) ss += __shfl_xor_sync(0xffffffffu, ss, o);
    float rstd = rsqrtf(ss * (1.0f / CDIM) + 1e-6f);
    #pragma unroll
    for (int q = 0; q < 6; q++) {
        int c = lane * 4 + q * 128;
        float4 gg = *(const float4*)(g + c);
        float4 bb4 = *(const float4*)(b + c);
        __half2 h0 = __floats2half2_rn((v[q*4+0] - mean) * rstd * gg.x + bb4.x,
                                       (v[q*4+1] - mean) * rstd * gg.y + bb4.y);
        __half2 h1 = __floats2half2_rn((v[q*4+2] - mean) * rstd * gg.z + bb4.z,
                                       (v[q*4+3] - mean) * rstd * gg.w + bb4.w);
        *(__half2*)(out + c) = h0;
        *(__half2*)(out + c + 2) = h1;
    }
}

// ---------------- FP16 mma.sync GEMM ----------------
// CTA 128x128, 256 threads, 8 warps (2M x 4N), warp 64x32, m16n8k16, 4-stage cp.async (k-slab 32).
// A: half [M][K] row-major. B: half2 k-pair interleaved [K/2][N].
// EPI: 0=bias->half; 1=bias+gelu->half; 2=bias+window-reverse+residual->f32; 3=bias+residual->f32
#define ASTRH 40                 // halfs per A row (32 + 8 pad) = 80B
#define BSTR2 136                // half2 per B kpair row (128 + 8 pad)
#define A_STAGE_B (128 * ASTRH * 2)     // 10240 B
#define B_STAGE_B (16 * BSTR2 * 4)      // 8704 B
#define NSTAGE 4
#define GEMM_SMEM_BYTES (NSTAGE * (A_STAGE_B + B_STAGE_B))

template<int EPI>
__global__ __launch_bounds__(256, 2)
void hgemm(const __half* __restrict__ A, const __half* __restrict__ B2,
           const float* __restrict__ bias, const float* __restrict__ R,
           void* __restrict__ Cc, int M, int N, int K) {
    extern __shared__ char smc[];
    __half* As = (__half*)smc;                                  // [NSTAGE][128][ASTRH]
    __half2* Bs = (__half2*)(smc + NSTAGE * A_STAGE_B);         // [NSTAGE][16][BSTR2]

    int tid = threadIdx.x, wid = tid >> 5, lane = tid & 31;
    int g = lane >> 2, c = lane & 3;
    int mw = (wid >> 2) * 64, nw = (wid & 3) * 32;
    int m0 = blockIdx.y * 128, n0 = blockIdx.x * 128;

    float acc[4][4][4];
    #pragma unroll
    for (int i = 0; i < 4; i++)
        #pragma unroll
        for (int j = 0; j < 4; j++)
            #pragma unroll
            for (int q = 0; q < 4; q++) acc[i][j][q] = 0.f;

    int arow = tid >> 1, achk = (tid & 1) * 16;   // 2 lanes/A-row, 32B each
    int bkrow = tid >> 4, bseg = (tid & 15) * 8;  // 16 lanes/B-kprow, 32B each (half2 units)

    auto loadStage = [&](int t) {
        int st = t % NSTAGE;
        __half* Ad = As + (size_t)st * 128 * ASTRH;
        int m = m0 + arow;
        bool v = m < M;
        const __half* src = v ? (A + (size_t)m * K + t * 32 + achk) : A;
        cp16(Ad + arow * ASTRH + achk,     src,             v ? 16 : 0);
        cp16(Ad + arow * ASTRH + achk + 8, v ? src + 8 : A, v ? 16 : 0);
        __half2* Bd = Bs + (size_t)st * 16 * BSTR2;
        const __half2* bsrc = (const __half2*)B2 + (size_t)(t * 16 + bkrow) * N + n0 + bseg;
        cp16(Bd + bkrow * BSTR2 + bseg,     bsrc,     16);
        cp16(Bd + bkrow * BSTR2 + bseg + 4, bsrc + 4, 16);
        CP_COMMIT();
    };

    int nk = K / 32;
    #pragma unroll
    for (int t = 0; t < NSTAGE - 1; t++) loadStage(t);

    for (int t = 0; t < nk; t++) {
        asm volatile("cp.async.wait_group %0;" :: "n"(NSTAGE - 2) : "memory");
        __syncthreads();
        if (t + NSTAGE - 1 < nk) loadStage(t + NSTAGE - 1);
        else CP_COMMIT();
        const __half* a_s = As + (size_t)(t % NSTAGE) * 128 * ASTRH;
        const __half2* b_s = Bs + (size_t)(t % NSTAGE) * 16 * BSTR2;
        #pragma unroll
        for (int kk = 0; kk < 2; kk++) {
            uint32_t af[4][4], bf[4][2];
            #pragma unroll
            for (int tm = 0; tm < 4; tm++) {
                const __half* ap = a_s + (mw + tm * 16 + g) * ASTRH + kk * 16 + 2 * c;
                af[tm][0] = *(const uint32_t*)(ap);
                af[tm][1] = *(const uint32_t*)(ap + 8 * ASTRH);
                af[tm][2] = *(const uint32_t*)(ap + 8);
                af[tm][3] = *(const uint32_t*)(ap + 8 * ASTRH + 8);
            }
            #pragma unroll
            for (int tn = 0; tn < 4; tn++) {
                const __half2* bp = b_s + (kk * 8 + c) * BSTR2 + nw + tn * 8 + g;
                bf[tn][0] = *(const uint32_t*)(bp);
                bf[tn][1] = *(const uint32_t*)(bp + 4 * BSTR2);
            }
            #pragma unroll
            for (int tm = 0; tm < 4; tm++)
                #pragma unroll
                for (int tn = 0; tn < 4; tn++)
                    mma_f16(acc[tm][tn], af[tm], bf[tn]);
        }
        __syncthreads();
    }

    // epilogue
    #pragma unroll
    for (int tm = 0; tm < 4; tm++) {
        #pragma unroll
        for (int half_ = 0; half_ < 2; half_++) {
            int m = m0 + mw + tm * 16 + g + half_ * 8;
            if (m >= M) continue;
            size_t obase = 0;
            const float* rbase = nullptr;
            bool valid = true;
            if (EPI == 2) {
                int bw = m / TOK, tt = m % TOK;
                int bb = bw / (NWH * NWW), rem = bw % (NWH * NWW);
                int wh = rem / NWW, ww = rem % NWW;
                int ii = tt / WS, jj = tt % WS;
                int h = wh * WS + ii, w = ww * WS + jj;
                if (h >= IMGH || w >= IMGW) valid = false;
                else { obase = ((size_t)(bb * IMGH + h) * IMGW + w) * CDIM; rbase = R + obase; }
            } else {
                obase = (size_t)m * N;
                if (EPI == 3) rbase = R + obase;
            }
            if (!valid) continue;
            #pragma unroll
            for (int tn = 0; tn < 4; tn++) {
                int n = n0 + nw + tn * 8 + 2 * c;
                float v0 = acc[tm][tn][half_ * 2 + 0] + bias[n];
                float v1 = acc[tm][tn][half_ * 2 + 1] + bias[n + 1];
                if (EPI == 0) {
                    *(__half2*)((__half*)Cc + obase + n) = __floats2half2_rn(v0, v1);
                } else if (EPI == 1) {
                    v0 = 0.5f * v0 * (1.0f + erff(v0 * 0.7071067811865476f));
                    v1 = 0.5f * v1 * (1.0f + erff(v1 * 0.7071067811865476f));
                    *(__half2*)((__half*)Cc + obase + n) = __floats2half2_rn(v0, v1);
                } else {
                    v0 += rbase[n];
                    v1 += rbase[n + 1];
                    *(float2*)((float*)Cc + obase + n) = make_float2(v0, v1);
                }
            }
        }
    }
}

// ---------------- windowed attention (half in / half out) ----------------
#define SM_QS   0
#define SM_VS   (TOK * 64)
#define SM_KS   (2 * TOK * 64)
#define SM_RH   (2 * TOK * 64 + TOK * 65)
#define SM_RW   (SM_RH + 27 * 65)
#define SM_PS   (SM_RW + 27 * 65)
#define SM_RHW  (SM_PS + 8 * 200)
#define SM_TOTAL_FLOATS (SM_RHW + 8 * 64)

__global__ void attn_kernel(const __half* __restrict__ qkv,
                            const float* __restrict__ relh,
                            const float* __restrict__ relw,
                            __half* __restrict__ attout) {
    extern __shared__ float smf[];
    float* qs = smf + SM_QS;
    float* vs = smf + SM_VS;
    float* ks = smf + SM_KS;
    float* Rh = smf + SM_RH;
    float* Rw = smf + SM_RW;
    float* Ps = smf + SM_PS;
    float* rhw = smf + SM_RHW;

    int blk = blockIdx.x;
    int bw = blk / NH, nh = blk % NH;
    int tid = threadIdx.x, lane = tid & 31, warp = tid >> 5;

    const __half* base = qkv + (size_t)bw * TOK * QKVN + nh * HD;
    for (int t4 = tid; t4 < TOK * 16; t4 += 256) {
        int t = t4 >> 4, c4 = (t4 & 15) * 4;
        const __half* p = base + (size_t)t * QKVN;
        float4 q4 = h4tof4(p + c4);
        float4 k4 = h4tof4(p + CDIM + c4);
        float4 v4 = h4tof4(p + 2 * CDIM + c4);
        *(float4*)(qs + t * 64 + c4) = q4;
        ks[t * 65 + c4 + 0] = k4.x;
        ks[t * 65 + c4 + 1] = k4.y;
        ks[t * 65 + c4 + 2] = k4.z;
        ks[t * 65 + c4 + 3] = k4.w;
        *(float4*)(vs + t * 64 + c4) = v4;
    }
    for (int idx = tid; idx < 27 * 64; idx += 256) {
        int rr = idx >> 6, c = idx & 63;
        Rh[rr * 65 + c] = relh[idx];
        Rw[rr * 65 + c] = relw[idx];
    }
    __syncthreads();

    const float scale = 0.125f;
    for (int qi = warp; qi < TOK; qi += 8) {
        int i = qi / WS, j = qi % WS;
        const float* qrow = qs + qi * 64;

        float rh = 0.f, rw = 0.f;
        if (lane < WS) {
            const float* rhrow = Rh + (i - lane + WS - 1) * 65;
            const float* rwrow = Rw + (j - lane + WS - 1) * 65;
            #pragma unroll 8
            for (int c = 0; c < 64; c++) {
                float qc = qrow[c];
                rh = fmaf(qc, rhrow[c], rh);
                rw = fmaf(qc, rwrow[c], rw);
            }
        }
        rhw[warp * 64 + lane] = rh;
        rhw[warp * 64 + 32 + lane] = rw;
        __syncwarp();

        float accv[7];
        #pragma unroll
        for (int m = 0; m < 7; m++) accv[m] = 0.f;
        #pragma unroll 4
        for (int c = 0; c < 64; c++) {
            float qc = qrow[c];
            #pragma unroll
            for (int m = 0; m < 7; m++) {
                int kj = lane + 32 * m;
                if (kj < TOK) accv[m] = fmaf(qc, ks[kj * 65 + c], accv[m]);
            }
        }
        float s[7];
        #pragma unroll
        for (int m = 0; m < 7; m++) {
            int kj = lane + 32 * m;
            if (kj < TOK) {
                int kk = kj / WS, ll = kj % WS;
                s[m] = accv[m] * scale + rhw[warp * 64 + kk] + rhw[warp * 64 + 32 + ll];
            } else {
                s[m] = -1e30f;
            }
        }
        float mx = -1e30f;
        #pragma unroll
        for (int m = 0; m < 7; m++) mx = fmaxf(mx, s[m]);
        #pragma unroll
        for (int o = 16; o > 0; o >>= 1) mx = fmaxf(mx, __shfl_xor_sync(0xffffffffu, mx, o));
        float p[7], sum = 0.f;
        #pragma unroll
        for (int m = 0; m < 7; m++) { p[m] = __expf(s[m] - mx); sum += p[m]; }
        #pragma unroll
        for (int o = 16; o > 0; o >>= 1) sum += __shfl_xor_sync(0xffffffffu, sum, o);
        float inv = __frcp_rn(sum);
        #pragma unroll
        for (int m = 0; m < 7; m++) {
            int kj = lane + 32 * m;
            if (kj < TOK) Ps[warp * 200 + kj] = p[m] * inv;
        }
        __syncwarp();

        float o0 = 0.f, o1 = 0.f;
        #pragma unroll 4
        for (int kj = 0; kj < TOK; kj++) {
            float pp = Ps[warp * 200 + kj];
            o0 = fmaf(pp, vs[kj * 64 + lane], o0);
            o1 = fmaf(pp, vs[kj * 64 + 32 + lane], o1);
        }
        __half* orow = attout + ((size_t)(bw * TOK + qi)) * CDIM + nh * HD;
        orow[lane] = __float2half_rn(o0);
        orow[lane + 32] = __float2half_rn(o1);
        __syncwarp();
    }
}

// ---------------- launch ----------------
extern "C" void kernel_launch(void* const* d_in, const int* in_sizes, int n_in,
                              void* d_out, int out_size) {
    const float* x       = (const float*)d_in[0];
    const float* ln1_g   = (const float*)d_in[1];
    const float* ln1_b   = (const float*)d_in[2];
    const float* w_qkv   = (const float*)d_in[3];
    const float* b_qkv   = (const float*)d_in[4];
    const float* w_proj  = (const float*)d_in[5];
    const float* b_proj  = (const float*)d_in[6];
    const float* relh    = (const float*)d_in[7];
    const float* relw    = (const float*)d_in[8];
    const float* ln2_g   = (const float*)d_in[9];
    const float* ln2_b   = (const float*)d_in[10];
    const float* w_fc1   = (const float*)d_in[11];
    const float* b_fc1   = (const float*)d_in[12];
    const float* w_fc2   = (const float*)d_in[13];
    const float* b_fc2   = (const float*)d_in[14];
    float* out = (float*)d_out;

    __half *win, *qkv, *att, *yln, *y1, *wqkv, *wproj, *wfc1, *wfc2;
    float *x2;
    cudaGetSymbolAddress((void**)&win, g_win);
    cudaGetSymbolAddress((void**)&qkv, g_qkv);
    cudaGetSymbolAddress((void**)&att, g_att);
    cudaGetSymbolAddress((void**)&x2,  g_x2);
    cudaGetSymbolAddress((void**)&yln, g_yln);
    cudaGetSymbolAddress((void**)&y1,  g_y1);
    cudaGetSymbolAddress((void**)&wqkv,  g_wqkv);
    cudaGetSymbolAddress((void**)&wproj, g_wproj);
    cudaGetSymbolAddress((void**)&wfc1,  g_wfc1);
    cudaGetSymbolAddress((void**)&wfc2,  g_wfc2);

    const int smem_attn = SM_TOTAL_FLOATS * 4;
    cudaFuncSetAttribute(attn_kernel, cudaFuncAttributeMaxDynamicSharedMemorySize, smem_attn);
    cudaFuncSetAttribute(hgemm<0>, cudaFuncAttributeMaxDynamicSharedMemorySize, GEMM_SMEM_BYTES);
    cudaFuncSetAttribute(hgemm<1>, cudaFuncAttributeMaxDynamicSharedMemorySize, GEMM_SMEM_BYTES);
    cudaFuncSetAttribute(hgemm<2>, cudaFuncAttributeMaxDynamicSharedMemorySize, GEMM_SMEM_BYTES);
    cudaFuncSetAttribute(hgemm<3>, cudaFuncAttributeMaxDynamicSharedMemorySize, GEMM_SMEM_BYTES);

    // 1) LN1 + window partition FIRST (ncu -s 5 -> 6th launch = qkv GEMM)
    ln1_win_kernel<<<(ROWS_WIN * 32 + 255) / 256, 256>>>(x, ln1_g, ln1_b, win);

    // weights -> half2 k-pair interleaved
    w2h_kernel<<<(CDIM / 2 * QKVN + 255) / 256, 256>>>(w_qkv, wqkv, CDIM, QKVN);
    w2h_kernel<<<(CDIM / 2 * CDIM + 255) / 256, 256>>>(w_proj, wproj, CDIM, CDIM);
    w2h_kernel<<<(CDIM / 2 * FFN + 255) / 256, 256>>>(w_fc1, wfc1, CDIM, FFN);
    w2h_kernel<<<(FFN / 2 * CDIM + 255) / 256, 256>>>(w_fc2, wfc2, FFN, CDIM);

    // 2) QKV GEMM [19600,768]x[768,2304] -> half
    hgemm<0><<<dim3(QKVN / 128, (ROWS_WIN + 127) / 128), 256, GEMM_SMEM_BYTES>>>(
        win, wqkv, b_qkv, nullptr, qkv, ROWS_WIN, QKVN, CDIM);

    // 3) attention
    attn_kernel<<<BW * NH, 256, smem_attn>>>(qkv, relh, relw, att);

    // 4) proj + window reverse + residual -> f32
    hgemm<2><<<dim3(CDIM / 128, (ROWS_WIN + 127) / 128), 256, GEMM_SMEM_BYTES>>>(
        att, wproj, b_proj, x, x2, ROWS_WIN, CDIM, CDIM);

    // 5) LN2 -> half
    ln2_kernel<<<(ROWS_IMG * 32 + 255) / 256, 256>>>(x2, ln2_g, ln2_b, yln);

    // 6) fc1 + gelu -> half
    hgemm<1><<<dim3(FFN / 128, ROWS_IMG / 128), 256, GEMM_SMEM_BYTES>>>(
        yln, wfc1, b_fc1, nullptr, y1, ROWS_IMG, FFN, CDIM);

    // 7) fc2 + residual -> out f32
    hgemm<3><<<dim3(CDIM / 128, ROWS_IMG / 128), 256, GEMM_SMEM_BYTES>>>(
        y1, wfc2, b_fc2, x2, out, ROWS_IMG, CDIM, FFN);
}

// round 8
// speedup vs baseline: 1.5565x; 1.0084x over previous
#include <cuda_runtime.h>
#include <cuda_fp16.h>
#include <math.h>
#include <stdint.h>

// ---------------- problem constants ----------------
#define BATCH 4
#define IMGH  64
#define IMGW  64
#define CDIM  768
#define WS    14
#define TOK   196
#define NH    12
#define HD    64
#define NWH   5
#define NWW   5
#define BW    100
#define ROWS_WIN 19600
#define ROWS_IMG 16384
#define QKVN  2304
#define FFN   3072

// ---------------- scratch ----------------
__device__ __half g_win[(size_t)ROWS_WIN * CDIM];
__device__ __half g_qkv[(size_t)ROWS_WIN * QKVN];
__device__ __half g_att[(size_t)ROWS_WIN * CDIM];
__device__ float  g_x2 [(size_t)ROWS_IMG * CDIM];
__device__ __half g_yln[(size_t)ROWS_IMG * CDIM];
__device__ __half g_y1 [(size_t)ROWS_IMG * FFN];
__device__ __half g_wqkv[(size_t)CDIM * QKVN];   // [K/2][N] half2 k-pair interleaved
__device__ __half g_wproj[(size_t)CDIM * CDIM];
__device__ __half g_wfc1[(size_t)CDIM * FFN];
__device__ __half g_wfc2[(size_t)FFN * CDIM];

// ---------------- helpers ----------------
__device__ __forceinline__ uint32_t smem_u32(const void* p) {
    uint32_t a;
    asm("{ .reg .u64 t; cvta.to.shared.u64 t, %1; cvt.u32.u64 %0, t; }" : "=r"(a) : "l"(p));
    return a;
}
__device__ __forceinline__ void cp16(void* sdst, const void* gsrc, int bytes) {
    uint32_t sa = smem_u32(sdst);
    asm volatile("cp.async.cg.shared.global [%0], [%1], 16, %2;" :: "r"(sa), "l"(gsrc), "r"(bytes));
}
#define CP_COMMIT() asm volatile("cp.async.commit_group;")

__device__ __forceinline__ void mma_f16(float c[4], const uint32_t a[4], const uint32_t b[2]) {
    asm volatile(
        "mma.sync.aligned.m16n8k16.row.col.f32.f16.f16.f32 "
        "{%0,%1,%2,%3}, {%4,%5,%6,%7}, {%8,%9}, {%0,%1,%2,%3};"
        : "+f"(c[0]), "+f"(c[1]), "+f"(c[2]), "+f"(c[3])
        : "r"(a[0]), "r"(a[1]), "r"(a[2]), "r"(a[3]), "r"(b[0]), "r"(b[1]));
}
__device__ __forceinline__ void ldmatrix_x4(uint32_t r[4], uint32_t addr) {
    asm volatile("ldmatrix.sync.aligned.m8n8.x4.shared.b16 {%0,%1,%2,%3}, [%4];"
                 : "=r"(r[0]), "=r"(r[1]), "=r"(r[2]), "=r"(r[3]) : "r"(addr));
}

__device__ __forceinline__ float4 h4tof4(const __half* p) {
    __half2 h0 = *(const __half2*)p;
    __half2 h1 = *(const __half2*)(p + 2);
    float2 a = __half22float2(h0), b = __half22float2(h1);
    return make_float4(a.x, a.y, b.x, b.y);
}

// ---------------- all weights -> half2 k-pair interleaved, one kernel ----------------
#define W1T ((CDIM / 2) * QKVN)
#define W2T ((CDIM / 2) * CDIM)
#define W3T ((CDIM / 2) * FFN)
#define W4T ((FFN / 2) * CDIM)
__global__ void w2h_all_kernel(const float* __restrict__ wq, const float* __restrict__ wp,
                               const float* __restrict__ w1, const float* __restrict__ w2,
                               __half* __restrict__ oq, __half* __restrict__ op,
                               __half* __restrict__ o1, __half* __restrict__ o2) {
    int idx = blockIdx.x * blockDim.x + threadIdx.x;
    const float* in; __half* out; int Nd, local;
    if (idx < W1T)                    { in = wq; out = oq; Nd = QKVN; local = idx; }
    else if (idx < W1T + W2T)         { in = wp; out = op; Nd = CDIM; local = idx - W1T; }
    else if (idx < W1T + W2T + W3T)   { in = w1; out = o1; Nd = FFN;  local = idx - W1T - W2T; }
    else if (idx < W1T + W2T + W3T + W4T) { in = w2; out = o2; Nd = CDIM; local = idx - W1T - W2T - W3T; }
    else return;
    int kp = local / Nd, n = local % Nd;
    float a = in[(size_t)(2 * kp) * Nd + n];
    float b = in[(size_t)(2 * kp + 1) * Nd + n];
    ((__half2*)out)[local] = __floats2half2_rn(a, b);
}

// ---------------- LN1 + window partition -> half ----------------
__global__ void ln1_win_kernel(const float* __restrict__ x,
                               const float* __restrict__ g,
                               const float* __restrict__ b,
                               __half* __restrict__ out_) {
    int warp = (blockIdx.x * blockDim.x + threadIdx.x) >> 5;
    int lane = threadIdx.x & 31;
    if (warp >= ROWS_WIN) return;
    int r = warp;
    int bw = r / TOK, t = r % TOK;
    int bb = bw / (NWH * NWW), rem = bw % (NWH * NWW);
    int wh = rem / NWW, ww = rem % NWW;
    int i = t / WS, j = t % WS;
    int h = wh * WS + i, w = ww * WS + j;
    __half* out = out_ + (size_t)r * CDIM;
    if (h >= IMGH || w >= IMGW) {
        uint2 z = make_uint2(0u, 0u);
        #pragma unroll
        for (int q = 0; q < 6; q++) *(uint2*)(out + lane * 4 + q * 128) = z;
        return;
    }
    const float* row = x + ((size_t)(bb * IMGH + h) * IMGW + w) * CDIM;
    float v[24];
    float s = 0.f;
    #pragma unroll
    for (int q = 0; q < 6; q++) {
        float4 f = *(const float4*)(row + lane * 4 + q * 128);
        v[q*4+0] = f.x; v[q*4+1] = f.y; v[q*4+2] = f.z; v[q*4+3] = f.w;
        s += f.x + f.y + f.z + f.w;
    }
    #pragma unroll
    for (int o = 16; o > 0; o >>= 1) s += __shfl_xor_sync(0xffffffffu, s, o);
    float mean = s * (1.0f / CDIM);
    float ss = 0.f;
    #pragma unroll
    for (int q = 0; q < 24; q++) { float d = v[q] - mean; ss += d * d; }
    #pragma unroll
    for (int o = 16; o > 0; o >>= 1) ss += __shfl_xor_sync(0xffffffffu, ss, o);
    float rstd = rsqrtf(ss * (1.0f / CDIM) + 1e-6f);
    #pragma unroll
    for (int q = 0; q < 6; q++) {
        int c = lane * 4 + q * 128;
        float4 gg = *(const float4*)(g + c);
        float4 bb4 = *(const float4*)(b + c);
        __half2 h0 = __floats2half2_rn((v[q*4+0] - mean) * rstd * gg.x + bb4.x,
                                       (v[q*4+1] - mean) * rstd * gg.y + bb4.y);
        __half2 h1 = __floats2half2_rn((v[q*4+2] - mean) * rstd * gg.z + bb4.z,
                                       (v[q*4+3] - mean) * rstd * gg.w + bb4.w);
        *(__half2*)(out + c) = h0;
        *(__half2*)(out + c + 2) = h1;
    }
}

// ---------------- LN2 -> half ----------------
__global__ void ln2_kernel(const float* __restrict__ x,
                           const float* __restrict__ g,
                           const float* __restrict__ b,
                           __half* __restrict__ out_) {
    int warp = (blockIdx.x * blockDim.x + threadIdx.x) >> 5;
    int lane = threadIdx.x & 31;
    if (warp >= ROWS_IMG) return;
    const float* row = x + (size_t)warp * CDIM;
    __half* out = out_ + (size_t)warp * CDIM;
    float v[24];
    float s = 0.f;
    #pragma unroll
    for (int q = 0; q < 6; q++) {
        float4 f = *(const float4*)(row + lane * 4 + q * 128);
        v[q*4+0] = f.x; v[q*4+1] = f.y; v[q*4+2] = f.z; v[q*4+3] = f.w;
        s += f.x + f.y + f.z + f.w;
    }
    #pragma unroll
    for (int o = 16; o > 0; o >>= 1) s += __shfl_xor_sync(0xffffffffu, s, o);
    float mean = s * (1.0f / CDIM);
    float ss = 0.f;
    #pragma unroll
    for (int q = 0; q < 24; q++) { float d = v[q] - mean; ss += d * d; }
    #pragma unroll
    for (int o = 16; o > 0; o >>= 1) ss += __shfl_xor_sync(0xffffffffu, ss, o);
    float rstd = rsqrtf(ss * (1.0f / CDIM) + 1e-6f);
    #pragma unroll
    for (int q = 0; q < 6; q++) {
        int c = lane * 4 + q * 128;
        float4 gg = *(const float4*)(g + c);
        float4 bb4 = *(const float4*)(b + c);
        __half2 h0 = __floats2half2_rn((v[q*4+0] - mean) * rstd * gg.x + bb4.x,
                                       (v[q*4+1] - mean) * rstd * gg.y + bb4.y);
        __half2 h1 = __floats2half2_rn((v[q*4+2] - mean) * rstd * gg.z + bb4.z,
                                       (v[q*4+3] - mean) * rstd * gg.w + bb4.w);
        *(__half2*)(out + c) = h0;
        *(__half2*)(out + c + 2) = h1;
    }
}

// ---------------- FP16 mma.sync GEMM (ldmatrix A, 5-stage, single-sync) ----------------
// CTA 128x128, 256 threads, 8 warps (2M x 4N), warp 64x32, m16n8k16, k-slab 32.
// A: half [M][K] row-major. B: half2 k-pair interleaved [K/2][N].
// EPI: 0=bias->half; 1=bias+gelu->half; 2=bias+window-reverse+residual->f32; 3=bias+residual->f32
#define ASTRH 40                 // halfs per A row (32 + 8 pad) = 80B
#define BSTR2 136                // half2 per B kpair row (128 + 8 pad)
#define A_STAGE_B (128 * ASTRH * 2)     // 10240 B
#define B_STAGE_B (16 * BSTR2 * 4)      // 8704 B
#define NSTAGE 5
#define GEMM_SMEM_BYTES (NSTAGE * (A_STAGE_B + B_STAGE_B))

template<int EPI>
__global__ __launch_bounds__(256, 2)
void hgemm(const __half* __restrict__ A, const __half* __restrict__ B2,
           const float* __restrict__ bias, const float* __restrict__ R,
           void* __restrict__ Cc, int M, int N, int K) {
    extern __shared__ char smc[];
    __half* As = (__half*)smc;                                  // [NSTAGE][128][ASTRH]
    __half2* Bs = (__half2*)(smc + NSTAGE * A_STAGE_B);         // [NSTAGE][16][BSTR2]
    uint32_t As_u32 = smem_u32(As);

    int tid = threadIdx.x, wid = tid >> 5, lane = tid & 31;
    int g = lane >> 2, c = lane & 3;
    int mw = (wid >> 2) * 64, nw = (wid & 3) * 32;
    int m0 = blockIdx.y * 128, n0 = blockIdx.x * 128;

    float acc[4][4][4];
    #pragma unroll
    for (int i = 0; i < 4; i++)
        #pragma unroll
        for (int j = 0; j < 4; j++)
            #pragma unroll
            for (int q = 0; q < 4; q++) acc[i][j][q] = 0.f;

    int arow = tid >> 1, achk = (tid & 1) * 16;   // 2 lanes/A-row, 32B each
    int bkrow = tid >> 4, bseg = (tid & 15) * 8;  // 16 lanes/B-kprow, 32B each (half2)

    // ldmatrix per-lane A row/col offset (halfs): row = mw + (lane&15), col = (lane>>4)*8
    uint32_t a_lm_off = (uint32_t)((mw + (lane & 15)) * ASTRH + (lane >> 4) * 8) * 2;

    auto loadStage = [&](int t) {
        int st = t % NSTAGE;
        __half* Ad = As + (size_t)st * 128 * ASTRH;
        int m = m0 + arow;
        bool v = m < M;
        const __half* src = v ? (A + (size_t)m * K + t * 32 + achk) : A;
        cp16(Ad + arow * ASTRH + achk,     src,             v ? 16 : 0);
        cp16(Ad + arow * ASTRH + achk + 8, v ? src + 8 : A, v ? 16 : 0);
        __half2* Bd = Bs + (size_t)st * 16 * BSTR2;
        const __half2* bsrc = (const __half2*)B2 + (size_t)(t * 16 + bkrow) * N + n0 + bseg;
        cp16(Bd + bkrow * BSTR2 + bseg,     bsrc,     16);
        cp16(Bd + bkrow * BSTR2 + bseg + 4, bsrc + 4, 16);
        CP_COMMIT();
    };

    int nk = K / 32;
    #pragma unroll
    for (int t = 0; t < NSTAGE - 1; t++) loadStage(t);

    for (int t = 0; t < nk; t++) {
        asm volatile("cp.async.wait_group %0;" :: "n"(NSTAGE - 2) : "memory");
        __syncthreads();
        if (t + NSTAGE - 1 < nk) loadStage(t + NSTAGE - 1);
        else CP_COMMIT();
        uint32_t a_base = As_u32 + (uint32_t)((t % NSTAGE) * A_STAGE_B) + a_lm_off;
        const __half2* b_s = Bs + (size_t)(t % NSTAGE) * 16 * BSTR2;
        #pragma unroll
        for (int kk = 0; kk < 2; kk++) {
            uint32_t af[4][4], bf[4][2];
            #pragma unroll
            for (int tm = 0; tm < 4; tm++)
                ldmatrix_x4(af[tm], a_base + (uint32_t)(tm * 16 * ASTRH + kk * 16) * 2);
            #pragma unroll
            for (int tn = 0; tn < 4; tn++) {
                const __half2* bp = b_s + (kk * 8 + c) * BSTR2 + nw + tn * 8 + g;
                bf[tn][0] = *(const uint32_t*)(bp);
                bf[tn][1] = *(const uint32_t*)(bp + 4 * BSTR2);
            }
            #pragma unroll
            for (int tm = 0; tm < 4; tm++)
                #pragma unroll
                for (int tn = 0; tn < 4; tn++)
                    mma_f16(acc[tm][tn], af[tm], bf[tn]);
        }
    }

    // epilogue
    #pragma unroll
    for (int tm = 0; tm < 4; tm++) {
        #pragma unroll
        for (int half_ = 0; half_ < 2; half_++) {
            int m = m0 + mw + tm * 16 + g + half_ * 8;
            if (m >= M) continue;
            size_t obase = 0;
            const float* rbase = nullptr;
            bool valid = true;
            if (EPI == 2) {
                int bw = m / TOK, tt = m % TOK;
                int bb = bw / (NWH * NWW), rem = bw % (NWH * NWW);
                int wh = rem / NWW, ww = rem % NWW;
                int ii = tt / WS, jj = tt % WS;
                int h = wh * WS + ii, w = ww * WS + jj;
                if (h >= IMGH || w >= IMGW) valid = false;
                else { obase = ((size_t)(bb * IMGH + h) * IMGW + w) * CDIM; rbase = R + obase; }
            } else {
                obase = (size_t)m * N;
                if (EPI == 3) rbase = R + obase;
            }
            if (!valid) continue;
            #pragma unroll
            for (int tn = 0; tn < 4; tn++) {
                int n = n0 + nw + tn * 8 + 2 * c;
                float v0 = acc[tm][tn][half_ * 2 + 0] + bias[n];
                float v1 = acc[tm][tn][half_ * 2 + 1] + bias[n + 1];
                if (EPI == 0) {
                    *(__half2*)((__half*)Cc + obase + n) = __floats2half2_rn(v0, v1);
                } else if (EPI == 1) {
                    v0 = 0.5f * v0 * (1.0f + erff(v0 * 0.7071067811865476f));
                    v1 = 0.5f * v1 * (1.0f + erff(v1 * 0.7071067811865476f));
                    *(__half2*)((__half*)Cc + obase + n) = __floats2half2_rn(v0, v1);
                } else {
                    v0 += rbase[n];
                    v1 += rbase[n + 1];
                    *(float2*)((float*)Cc + obase + n) = make_float2(v0, v1);
                }
            }
        }
    }
}

// ---------------- windowed attention (half in / half out) ----------------
#define SM_QS   0
#define SM_VS   (TOK * 64)
#define SM_KS   (2 * TOK * 64)
#define SM_RH   (2 * TOK * 64 + TOK * 65)
#define SM_RW   (SM_RH + 27 * 65)
#define SM_PS   (SM_RW + 27 * 65)
#define SM_RHW  (SM_PS + 8 * 200)
#define SM_TOTAL_FLOATS (SM_RHW + 8 * 64)

__global__ void attn_kernel(const __half* __restrict__ qkv,
                            const float* __restrict__ relh,
                            const float* __restrict__ relw,
                            __half* __restrict__ attout) {
    extern __shared__ float smf[];
    float* qs = smf + SM_QS;
    float* vs = smf + SM_VS;
    float* ks = smf + SM_KS;
    float* Rh = smf + SM_RH;
    float* Rw = smf + SM_RW;
    float* Ps = smf + SM_PS;
    float* rhw = smf + SM_RHW;

    int blk = blockIdx.x;
    int bw = blk / NH, nh = blk % NH;
    int tid = threadIdx.x, lane = tid & 31, warp = tid >> 5;

    const __half* base = qkv + (size_t)bw * TOK * QKVN + nh * HD;
    for (int t4 = tid; t4 < TOK * 16; t4 += 256) {
        int t = t4 >> 4, c4 = (t4 & 15) * 4;
        const __half* p = base + (size_t)t * QKVN;
        float4 q4 = h4tof4(p + c4);
        float4 k4 = h4tof4(p + CDIM + c4);
        float4 v4 = h4tof4(p + 2 * CDIM + c4);
        *(float4*)(qs + t * 64 + c4) = q4;
        ks[t * 65 + c4 + 0] = k4.x;
        ks[t * 65 + c4 + 1] = k4.y;
        ks[t * 65 + c4 + 2] = k4.z;
        ks[t * 65 + c4 + 3] = k4.w;
        *(float4*)(vs + t * 64 + c4) = v4;
    }
    for (int idx = tid; idx < 27 * 64; idx += 256) {
        int rr = idx >> 6, c = idx & 63;
        Rh[rr * 65 + c] = relh[idx];
        Rw[rr * 65 + c] = relw[idx];
    }
    __syncthreads();

    const float scale = 0.125f;
    for (int qi = warp; qi < TOK; qi += 8) {
        int i = qi / WS, j = qi % WS;
        const float* qrow = qs + qi * 64;

        float rh = 0.f, rw = 0.f;
        if (lane < WS) {
            const float* rhrow = Rh + (i - lane + WS - 1) * 65;
            const float* rwrow = Rw + (j - lane + WS - 1) * 65;
            #pragma unroll 8
            for (int c = 0; c < 64; c++) {
                float qc = qrow[c];
                rh = fmaf(qc, rhrow[c], rh);
                rw = fmaf(qc, rwrow[c], rw);
            }
        }
        rhw[warp * 64 + lane] = rh;
        rhw[warp * 64 + 32 + lane] = rw;
        __syncwarp();

        float accv[7];
        #pragma unroll
        for (int m = 0; m < 7; m++) accv[m] = 0.f;
        #pragma unroll 4
        for (int c = 0; c < 64; c++) {
            float qc = qrow[c];
            #pragma unroll
            for (int m = 0; m < 7; m++) {
                int kj = lane + 32 * m;
                if (kj < TOK) accv[m] = fmaf(qc, ks[kj * 65 + c], accv[m]);
            }
        }
        float s[7];
        #pragma unroll
        for (int m = 0; m < 7; m++) {
            int kj = lane + 32 * m;
            if (kj < TOK) {
                int kk = kj / WS, ll = kj % WS;
                s[m] = accv[m] * scale + rhw[warp * 64 + kk] + rhw[warp * 64 + 32 + ll];
            } else {
                s[m] = -1e30f;
            }
        }
        float mx = -1e30f;
        #pragma unroll
        for (int m = 0; m < 7; m++) mx = fmaxf(mx, s[m]);
        #pragma unroll
        for (int o = 16; o > 0; o >>= 1) mx = fmaxf(mx, __shfl_xor_sync(0xffffffffu, mx, o));
        float p[7], sum = 0.f;
        #pragma unroll
        for (int m = 0; m < 7; m++) { p[m] = __expf(s[m] - mx); sum += p[m]; }
        #pragma unroll
        for (int o = 16; o > 0; o >>= 1) sum += __shfl_xor_sync(0xffffffffu, sum, o);
        float inv = __frcp_rn(sum);
        #pragma unroll
        for (int m = 0; m < 7; m++) {
            int kj = lane + 32 * m;
            if (kj < TOK) Ps[warp * 200 + kj] = p[m] * inv;
        }
        __syncwarp();

        float o0 = 0.f, o1 = 0.f;
        #pragma unroll 4
        for (int kj = 0; kj < TOK; kj++) {
            float pp = Ps[warp * 200 + kj];
            o0 = fmaf(pp, vs[kj * 64 + lane], o0);
            o1 = fmaf(pp, vs[kj * 64 + 32 + lane], o1);
        }
        __half* orow = attout + ((size_t)(bw * TOK + qi)) * CDIM + nh * HD;
        orow[lane] = __float2half_rn(o0);
        orow[lane + 32] = __float2half_rn(o1);
        __syncwarp();
    }
}

// ---------------- launch ----------------
extern "C" void kernel_launch(void* const* d_in, const int* in_sizes, int n_in,
                              void* d_out, int out_size) {
    const float* x       = (const float*)d_in[0];
    const float* ln1_g   = (const float*)d_in[1];
    const float* ln1_b   = (const float*)d_in[2];
    const float* w_qkv   = (const float*)d_in[3];
    const float* b_qkv   = (const float*)d_in[4];
    const float* w_proj  = (const float*)d_in[5];
    const float* b_proj  = (const float*)d_in[6];
    const float* relh    = (const float*)d_in[7];
    const float* relw    = (const float*)d_in[8];
    const float* ln2_g   = (const float*)d_in[9];
    const float* ln2_b   = (const float*)d_in[10];
    const float* w_fc1   = (const float*)d_in[11];
    const float* b_fc1   = (const float*)d_in[12];
    const float* w_fc2   = (const float*)d_in[13];
    const float* b_fc2   = (const float*)d_in[14];
    float* out = (float*)d_out;

    __half *win, *qkv, *att, *yln, *y1, *wqkv, *wproj, *wfc1, *wfc2;
    float *x2;
    cudaGetSymbolAddress((void**)&win, g_win);
    cudaGetSymbolAddress((void**)&qkv, g_qkv);
    cudaGetSymbolAddress((void**)&att, g_att);
    cudaGetSymbolAddress((void**)&x2,  g_x2);
    cudaGetSymbolAddress((void**)&yln, g_yln);
    cudaGetSymbolAddress((void**)&y1,  g_y1);
    cudaGetSymbolAddress((void**)&wqkv,  g_wqkv);
    cudaGetSymbolAddress((void**)&wproj, g_wproj);
    cudaGetSymbolAddress((void**)&wfc1,  g_wfc1);
    cudaGetSymbolAddress((void**)&wfc2,  g_wfc2);

    const int smem_attn = SM_TOTAL_FLOATS * 4;
    cudaFuncSetAttribute(attn_kernel, cudaFuncAttributeMaxDynamicSharedMemorySize, smem_attn);
    cudaFuncSetAttribute(hgemm<0>, cudaFuncAttributeMaxDynamicSharedMemorySize, GEMM_SMEM_BYTES);
    cudaFuncSetAttribute(hgemm<1>, cudaFuncAttributeMaxDynamicSharedMemorySize, GEMM_SMEM_BYTES);
    cudaFuncSetAttribute(hgemm<2>, cudaFuncAttributeMaxDynamicSharedMemorySize, GEMM_SMEM_BYTES);
    cudaFuncSetAttribute(hgemm<3>, cudaFuncAttributeMaxDynamicSharedMemorySize, GEMM_SMEM_BYTES);

    // (1) all weights -> half2 interleaved
    int wtot = W1T + W2T + W3T + W4T;
    w2h_all_kernel<<<(wtot + 255) / 256, 256>>>(w_qkv, w_proj, w_fc1, w_fc2,
                                                wqkv, wproj, wfc1, wfc2);

    // (2) LN1 + window partition
    ln1_win_kernel<<<(ROWS_WIN * 32 + 255) / 256, 256>>>(x, ln1_g, ln1_b, win);

    // (3) QKV GEMM -> half
    hgemm<0><<<dim3(QKVN / 128, (ROWS_WIN + 127) / 128), 256, GEMM_SMEM_BYTES>>>(
        win, wqkv, b_qkv, nullptr, qkv, ROWS_WIN, QKVN, CDIM);

    // (4) attention
    attn_kernel<<<BW * NH, 256, smem_attn>>>(qkv, relh, relw, att);

    // (5) proj + window reverse + residual -> f32   [ncu capture target]
    hgemm<2><<<dim3(CDIM / 128, (ROWS_WIN + 127) / 128), 256, GEMM_SMEM_BYTES>>>(
        att, wproj, b_proj, x, x2, ROWS_WIN, CDIM, CDIM);

    // (6) LN2 -> half
    ln2_kernel<<<(ROWS_IMG * 32 + 255) / 256, 256>>>(x2, ln2_g, ln2_b, yln);

    // (7) fc1 + gelu -> half
    hgemm<1><<<dim3(FFN / 128, ROWS_IMG / 128), 256, GEMM_SMEM_BYTES>>>(
        yln, wfc1, b_fc1, nullptr, y1, ROWS_IMG, FFN, CDIM);

    // (8) fc2 + residual -> out f32
    hgemm<3><<<dim3(CDIM / 128, ROWS_IMG / 128), 256, GEMM_SMEM_BYTES>>>(
        y1, wfc2, b_fc2, x2, out, ROWS_IMG, CDIM, FFN);
}

// round 9
// speedup vs baseline: 1.9356x; 1.2435x over previous
#include <cuda_runtime.h>
#include <cuda_fp16.h>
#include <math.h>
#include <stdint.h>

// ---------------- problem constants ----------------
#define BATCH 4
#define IMGH  64
#define IMGW  64
#define CDIM  768
#define WS    14
#define TOK   196
#define NH    12
#define HD    64
#define NWH   5
#define NWW   5
#define BW    100
#define ROWS_WIN 19600
#define ROWS_IMG 16384
#define QKVN  2304
#define FFN   3072

// ---------------- scratch ----------------
__device__ __half g_win[(size_t)ROWS_WIN * CDIM];
__device__ __half g_qkv[(size_t)ROWS_WIN * QKVN];
__device__ __half g_att[(size_t)ROWS_WIN * CDIM];
__device__ float  g_x2 [(size_t)ROWS_IMG * CDIM];
__device__ __half g_yln[(size_t)ROWS_IMG * CDIM];
__device__ __half g_y1 [(size_t)ROWS_IMG * FFN];
__device__ __half g_wqkv[(size_t)CDIM * QKVN];   // [K/2][N] half2 k-pair interleaved
__device__ __half g_wproj[(size_t)CDIM * CDIM];
__device__ __half g_wfc1[(size_t)CDIM * FFN];
__device__ __half g_wfc2[(size_t)FFN * CDIM];

// ---------------- helpers ----------------
__device__ __forceinline__ uint32_t smem_u32(const void* p) {
    uint32_t a;
    asm("{ .reg .u64 t; cvta.to.shared.u64 t, %1; cvt.u32.u64 %0, t; }" : "=r"(a) : "l"(p));
    return a;
}
__device__ __forceinline__ void cp16(void* sdst, const void* gsrc, int bytes) {
    uint32_t sa = smem_u32(sdst);
    asm volatile("cp.async.cg.shared.global [%0], [%1], 16, %2;" :: "r"(sa), "l"(gsrc), "r"(bytes));
}
#define CP_COMMIT() asm volatile("cp.async.commit_group;")

__device__ __forceinline__ void mma_f16(float c[4], const uint32_t a[4], const uint32_t b[2]) {
    asm volatile(
        "mma.sync.aligned.m16n8k16.row.col.f32.f16.f16.f32 "
        "{%0,%1,%2,%3}, {%4,%5,%6,%7}, {%8,%9}, {%0,%1,%2,%3};"
        : "+f"(c[0]), "+f"(c[1]), "+f"(c[2]), "+f"(c[3])
        : "r"(a[0]), "r"(a[1]), "r"(a[2]), "r"(a[3]), "r"(b[0]), "r"(b[1]));
}
__device__ __forceinline__ void ldmatrix_x4(uint32_t r[4], uint32_t addr) {
    asm volatile("ldmatrix.sync.aligned.m8n8.x4.shared.b16 {%0,%1,%2,%3}, [%4];"
                 : "=r"(r[0]), "=r"(r[1]), "=r"(r[2]), "=r"(r[3]) : "r"(addr));
}

// ---------------- all weights -> half2 k-pair interleaved ----------------
#define W1T ((CDIM / 2) * QKVN)
#define W2T ((CDIM / 2) * CDIM)
#define W3T ((CDIM / 2) * FFN)
#define W4T ((FFN / 2) * CDIM)
__global__ void w2h_all_kernel(const float* __restrict__ wq, const float* __restrict__ wp,
                               const float* __restrict__ w1, const float* __restrict__ w2,
                               __half* __restrict__ oq, __half* __restrict__ op,
                               __half* __restrict__ o1, __half* __restrict__ o2) {
    int idx = blockIdx.x * blockDim.x + threadIdx.x;
    const float* in; __half* out; int Nd, local;
    if (idx < W1T)                    { in = wq; out = oq; Nd = QKVN; local = idx; }
    else if (idx < W1T + W2T)         { in = wp; out = op; Nd = CDIM; local = idx - W1T; }
    else if (idx < W1T + W2T + W3T)   { in = w1; out = o1; Nd = FFN;  local = idx - W1T - W2T; }
    else if (idx < W1T + W2T + W3T + W4T) { in = w2; out = o2; Nd = CDIM; local = idx - W1T - W2T - W3T; }
    else return;
    int kp = local / Nd, n = local % Nd;
    float a = in[(size_t)(2 * kp) * Nd + n];
    float b = in[(size_t)(2 * kp + 1) * Nd + n];
    ((__half2*)out)[local] = __floats2half2_rn(a, b);
}

// ---------------- LN1 + window partition -> half ----------------
__global__ void ln1_win_kernel(const float* __restrict__ x,
                               const float* __restrict__ g,
                               const float* __restrict__ b,
                               __half* __restrict__ out_) {
    int warp = (blockIdx.x * blockDim.x + threadIdx.x) >> 5;
    int lane = threadIdx.x & 31;
    if (warp >= ROWS_WIN) return;
    int r = warp;
    int bw = r / TOK, t = r % TOK;
    int bb = bw / (NWH * NWW), rem = bw % (NWH * NWW);
    int wh = rem / NWW, ww = rem % NWW;
    int i = t / WS, j = t % WS;
    int h = wh * WS + i, w = ww * WS + j;
    __half* out = out_ + (size_t)r * CDIM;
    if (h >= IMGH || w >= IMGW) {
        uint2 z = make_uint2(0u, 0u);
        #pragma unroll
        for (int q = 0; q < 6; q++) *(uint2*)(out + lane * 4 + q * 128) = z;
        return;
    }
    const float* row = x + ((size_t)(bb * IMGH + h) * IMGW + w) * CDIM;
    float v[24];
    float s = 0.f;
    #pragma unroll
    for (int q = 0; q < 6; q++) {
        float4 f = *(const float4*)(row + lane * 4 + q * 128);
        v[q*4+0] = f.x; v[q*4+1] = f.y; v[q*4+2] = f.z; v[q*4+3] = f.w;
        s += f.x + f.y + f.z + f.w;
    }
    #pragma unroll
    for (int o = 16; o > 0; o >>= 1) s += __shfl_xor_sync(0xffffffffu, s, o);
    float mean = s * (1.0f / CDIM);
    float ss = 0.f;
    #pragma unroll
    for (int q = 0; q < 24; q++) { float d = v[q] - mean; ss += d * d; }
    #pragma unroll
    for (int o = 16; o > 0; o >>= 1) ss += __shfl_xor_sync(0xffffffffu, ss, o);
    float rstd = rsqrtf(ss * (1.0f / CDIM) + 1e-6f);
    #pragma unroll
    for (int q = 0; q < 6; q++) {
        int c = lane * 4 + q * 128;
        float4 gg = *(const float4*)(g + c);
        float4 bb4 = *(const float4*)(b + c);
        __half2 h0 = __floats2half2_rn((v[q*4+0] - mean) * rstd * gg.x + bb4.x,
                                       (v[q*4+1] - mean) * rstd * gg.y + bb4.y);
        __half2 h1 = __floats2half2_rn((v[q*4+2] - mean) * rstd * gg.z + bb4.z,
                                       (v[q*4+3] - mean) * rstd * gg.w + bb4.w);
        *(__half2*)(out + c) = h0;
        *(__half2*)(out + c + 2) = h1;
    }
}

// ---------------- LN2 -> half ----------------
__global__ void ln2_kernel(const float* __restrict__ x,
                           const float* __restrict__ g,
                           const float* __restrict__ b,
                           __half* __restrict__ out_) {
    int warp = (blockIdx.x * blockDim.x + threadIdx.x) >> 5;
    int lane = threadIdx.x & 31;
    if (warp >= ROWS_IMG) return;
    const float* row = x + (size_t)warp * CDIM;
    __half* out = out_ + (size_t)warp * CDIM;
    float v[24];
    float s = 0.f;
    #pragma unroll
    for (int q = 0; q < 6; q++) {
        float4 f = *(const float4*)(row + lane * 4 + q * 128);
        v[q*4+0] = f.x; v[q*4+1] = f.y; v[q*4+2] = f.z; v[q*4+3] = f.w;
        s += f.x + f.y + f.z + f.w;
    }
    #pragma unroll
    for (int o = 16; o > 0; o >>= 1) s += __shfl_xor_sync(0xffffffffu, s, o);
    float mean = s * (1.0f / CDIM);
    float ss = 0.f;
    #pragma unroll
    for (int q = 0; q < 24; q++) { float d = v[q] - mean; ss += d * d; }
    #pragma unroll
    for (int o = 16; o > 0; o >>= 1) ss += __shfl_xor_sync(0xffffffffu, ss, o);
    float rstd = rsqrtf(ss * (1.0f / CDIM) + 1e-6f);
    #pragma unroll
    for (int q = 0; q < 6; q++) {
        int c = lane * 4 + q * 128;
        float4 gg = *(const float4*)(g + c);
        float4 bb4 = *(const float4*)(b + c);
        __half2 h0 = __floats2half2_rn((v[q*4+0] - mean) * rstd * gg.x + bb4.x,
                                       (v[q*4+1] - mean) * rstd * gg.y + bb4.y);
        __half2 h1 = __floats2half2_rn((v[q*4+2] - mean) * rstd * gg.z + bb4.z,
                                       (v[q*4+3] - mean) * rstd * gg.w + bb4.w);
        *(__half2*)(out + c) = h0;
        *(__half2*)(out + c + 2) = h1;
    }
}

// ---------------- FP16 mma.sync GEMM (k-slab 64, 3-stage, single-sync) ----------------
// CTA 128x128, 256 threads, 8 warps (2M x 4N), warp 64x32, m16n8k16.
// A: half [M][K] row-major. B: half2 k-pair interleaved [K/2][N].
// EPI: 0=bias->half; 1=bias+gelu->half; 2=bias+window-reverse+residual->f32; 3=bias+residual->f32
#define ASTRH 72                 // halfs per A row (64 + 8 pad) = 144B
#define BSTR2 136                // half2 per B kpair row (128 + 8 pad)
#define A_STAGE_B (128 * ASTRH * 2)     // 18432 B
#define B_STAGE_B (32 * BSTR2 * 4)      // 17408 B
#define NSTAGE 3
#define GEMM_SMEM_BYTES (NSTAGE * (A_STAGE_B + B_STAGE_B))   // 107520

template<int EPI>
__global__ __launch_bounds__(256, 2)
void hgemm(const __half* __restrict__ A, const __half* __restrict__ B2,
           const float* __restrict__ bias, const float* __restrict__ R,
           void* __restrict__ Cc, int M, int N, int K) {
    extern __shared__ char smc[];
    __half* As = (__half*)smc;                                  // [NSTAGE][128][ASTRH]
    __half2* Bs = (__half2*)(smc + NSTAGE * A_STAGE_B);         // [NSTAGE][32][BSTR2]
    uint32_t As_u32 = smem_u32(As);

    int tid = threadIdx.x, wid = tid >> 5, lane = tid & 31;
    int g = lane >> 2, c = lane & 3;
    int mw = (wid >> 2) * 64, nw = (wid & 3) * 32;
    int m0 = blockIdx.y * 128, n0 = blockIdx.x * 128;

    float acc[4][4][4];
    #pragma unroll
    for (int i = 0; i < 4; i++)
        #pragma unroll
        for (int j = 0; j < 4; j++)
            #pragma unroll
            for (int q = 0; q < 4; q++) acc[i][j][q] = 0.f;

    int arow = tid >> 2, achk = (tid & 3) * 16;   // 4 lanes/A-row, 2 cp16 (32B) each
    int bkrow = tid >> 3, bseg = (tid & 7) * 16;  // 8 lanes/B-kprow, 4 cp16 (64B) each

    uint32_t a_lm_off = (uint32_t)((mw + (lane & 15)) * ASTRH + (lane >> 4) * 8) * 2;

    auto loadStage = [&](int t) {
        int st = t % NSTAGE;
        __half* Ad = As + (size_t)st * 128 * ASTRH;
        #pragma unroll
        for (int p = 0; p < 2; p++) {
            int r = arow + p * 64;
            int m = m0 + r;
            bool v = m < M;
            const __half* src = v ? (A + (size_t)m * K + t * 64 + achk) : A;
            cp16(Ad + r * ASTRH + achk,     src,             v ? 16 : 0);
            cp16(Ad + r * ASTRH + achk + 8, v ? src + 8 : A, v ? 16 : 0);
        }
        __half2* Bd = Bs + (size_t)st * 32 * BSTR2;
        const __half2* bsrc = (const __half2*)B2 + (size_t)(t * 32 + bkrow) * N + n0 + bseg;
        #pragma unroll
        for (int i = 0; i < 4; i++)
            cp16(Bd + bkrow * BSTR2 + bseg + 4 * i, bsrc + 4 * i, 16);
        CP_COMMIT();
    };

    int nk = K / 64;
    #pragma unroll
    for (int t = 0; t < NSTAGE - 1; t++) loadStage(t);

    for (int t = 0; t < nk; t++) {
        asm volatile("cp.async.wait_group %0;" :: "n"(NSTAGE - 2) : "memory");
        __syncthreads();
        if (t + NSTAGE - 1 < nk) loadStage(t + NSTAGE - 1);
        else CP_COMMIT();
        uint32_t a_base = As_u32 + (uint32_t)((t % NSTAGE) * A_STAGE_B) + a_lm_off;
        const __half2* b_s = Bs + (size_t)(t % NSTAGE) * 32 * BSTR2;
        #pragma unroll
        for (int kk = 0; kk < 4; kk++) {
            uint32_t af[4][4], bf[4][2];
            #pragma unroll
            for (int tm = 0; tm < 4; tm++)
                ldmatrix_x4(af[tm], a_base + (uint32_t)(tm * 16 * ASTRH + kk * 16) * 2);
            #pragma unroll
            for (int tn = 0; tn < 4; tn++) {
                const __half2* bp = b_s + (kk * 8 + c) * BSTR2 + nw + tn * 8 + g;
                bf[tn][0] = *(const uint32_t*)(bp);
                bf[tn][1] = *(const uint32_t*)(bp + 4 * BSTR2);
            }
            #pragma unroll
            for (int tm = 0; tm < 4; tm++)
                #pragma unroll
                for (int tn = 0; tn < 4; tn++)
                    mma_f16(acc[tm][tn], af[tm], bf[tn]);
        }
    }

    // epilogue
    #pragma unroll
    for (int tm = 0; tm < 4; tm++) {
        #pragma unroll
        for (int half_ = 0; half_ < 2; half_++) {
            int m = m0 + mw + tm * 16 + g + half_ * 8;
            if (m >= M) continue;
            size_t obase = 0;
            const float* rbase = nullptr;
            bool valid = true;
            if (EPI == 2) {
                int bw = m / TOK, tt = m % TOK;
                int bb = bw / (NWH * NWW), rem = bw % (NWH * NWW);
                int wh = rem / NWW, ww = rem % NWW;
                int ii = tt / WS, jj = tt % WS;
                int h = wh * WS + ii, w = ww * WS + jj;
                if (h >= IMGH || w >= IMGW) valid = false;
                else { obase = ((size_t)(bb * IMGH + h) * IMGW + w) * CDIM; rbase = R + obase; }
            } else {
                obase = (size_t)m * N;
                if (EPI == 3) rbase = R + obase;
            }
            if (!valid) continue;
            #pragma unroll
            for (int tn = 0; tn < 4; tn++) {
                int n = n0 + nw + tn * 8 + 2 * c;
                float v0 = acc[tm][tn][half_ * 2 + 0] + bias[n];
                float v1 = acc[tm][tn][half_ * 2 + 1] + bias[n + 1];
                if (EPI == 0) {
                    *(__half2*)((__half*)Cc + obase + n) = __floats2half2_rn(v0, v1);
                } else if (EPI == 1) {
                    v0 = 0.5f * v0 * (1.0f + erff(v0 * 0.7071067811865476f));
                    v1 = 0.5f * v1 * (1.0f + erff(v1 * 0.7071067811865476f));
                    *(__half2*)((__half*)Cc + obase + n) = __floats2half2_rn(v0, v1);
                } else {
                    v0 += rbase[n];
                    v1 += rbase[n + 1];
                    *(float2*)((float*)Cc + obase + n) = make_float2(v0, v1);
                }
            }
        }
    }
}

// ---------------- windowed attention (half2 smem, fp32 compute, 2 CTA/SM) ----------------
// byte offsets into dynamic smem
#define AT_QS   0                          // half2 [196][32]  25088 B
#define AT_VS   25088                      // half2 [196][32]  25088 B
#define AT_KS   50176                      // half2 [196][33]  25872 B
#define AT_RH   76048                      // float [27][66]    7128 B
#define AT_RW   83176                      // float [27][66]    7128 B
#define AT_PS   90304                      // float [8][200]    6400 B
#define AT_RHW  96704                      // float [8][64]     2048 B
#define ATTN_SMEM_BYTES 98752

__global__ __launch_bounds__(256, 2)
void attn_kernel(const __half* __restrict__ qkv,
                 const float* __restrict__ relh,
                 const float* __restrict__ relw,
                 __half* __restrict__ attout) {
    extern __shared__ char smc[];
    __half2* qs2 = (__half2*)(smc + AT_QS);
    __half2* vs2 = (__half2*)(smc + AT_VS);
    __half2* ks2 = (__half2*)(smc + AT_KS);
    float* Rh  = (float*)(smc + AT_RH);
    float* Rw  = (float*)(smc + AT_RW);
    float* Ps  = (float*)(smc + AT_PS);
    float* rhw = (float*)(smc + AT_RHW);

    int blk = blockIdx.x;
    int bw = blk / NH, nh = blk % NH;
    int tid = threadIdx.x, lane = tid & 31, warp = tid >> 5;

    const __half* base = qkv + (size_t)bw * TOK * QKVN + nh * HD;
    // load q/k/v: 8 chunks of 4 half2 per token
    for (int t4 = tid; t4 < TOK * 8; t4 += 256) {
        int t = t4 >> 3, cp4 = (t4 & 7) * 4;   // half2 index
        const __half* p = base + (size_t)t * QKVN + cp4 * 2;
        uint4 qv = *(const uint4*)(p);
        uint4 kv = *(const uint4*)(p + CDIM);
        uint4 vv = *(const uint4*)(p + 2 * CDIM);
        *(uint4*)(qs2 + t * 32 + cp4) = qv;
        *(uint4*)(vs2 + t * 32 + cp4) = vv;
        uint32_t* kd = (uint32_t*)(ks2 + t * 33 + cp4);
        kd[0] = kv.x; kd[1] = kv.y; kd[2] = kv.z; kd[3] = kv.w;
    }
    for (int idx = tid; idx < 27 * 64; idx += 256) {
        int rr = idx >> 6, cc = idx & 63;
        Rh[rr * 66 + cc] = relh[idx];
        Rw[rr * 66 + cc] = relw[idx];
    }
    __syncthreads();

    const float scale = 0.125f;
    for (int qi = warp; qi < TOK; qi += 8) {
        int i = qi / WS, j = qi % WS;
        const __half2* qrow2 = qs2 + qi * 32;

        // decomposed rel-pos dots (lanes 0..13)
        float rh = 0.f, rw = 0.f;
        if (lane < WS) {
            const float* rhrow = Rh + (i - lane + WS - 1) * 66;
            const float* rwrow = Rw + (j - lane + WS - 1) * 66;
            #pragma unroll 8
            for (int cp = 0; cp < 32; cp++) {
                float2 qf = __half22float2(qrow2[cp]);
                float2 hh = *(const float2*)(rhrow + 2 * cp);
                float2 wwv = *(const float2*)(rwrow + 2 * cp);
                rh = fmaf(qf.x, hh.x, fmaf(qf.y, hh.y, rh));
                rw = fmaf(qf.x, wwv.x, fmaf(qf.y, wwv.y, rw));
            }
        }
        rhw[warp * 64 + lane] = rh;
        rhw[warp * 64 + 32 + lane] = rw;
        __syncwarp();

        // q . k^T
        float accv[7];
        #pragma unroll
        for (int m = 0; m < 7; m++) accv[m] = 0.f;
        #pragma unroll 4
        for (int cp = 0; cp < 32; cp++) {
            float2 qf = __half22float2(qrow2[cp]);
            #pragma unroll
            for (int m = 0; m < 7; m++) {
                int kj = lane + 32 * m;
                if (kj < TOK) {
                    float2 kf = __half22float2(ks2[kj * 33 + cp]);
                    accv[m] = fmaf(qf.x, kf.x, fmaf(qf.y, kf.y, accv[m]));
                }
            }
        }
        float s[7];
        #pragma unroll
        for (int m = 0; m < 7; m++) {
            int kj = lane + 32 * m;
            if (kj < TOK) {
                int kk = kj / WS, ll = kj % WS;
                s[m] = accv[m] * scale + rhw[warp * 64 + kk] + rhw[warp * 64 + 32 + ll];
            } else {
                s[m] = -1e30f;
            }
        }
        float mx = -1e30f;
        #pragma unroll
        for (int m = 0; m < 7; m++) mx = fmaxf(mx, s[m]);
        #pragma unroll
        for (int o = 16; o > 0; o >>= 1) mx = fmaxf(mx, __shfl_xor_sync(0xffffffffu, mx, o));
        float p[7], sum = 0.f;
        #pragma unroll
        for (int m = 0; m < 7; m++) { p[m] = __expf(s[m] - mx); sum += p[m]; }
        #pragma unroll
        for (int o = 16; o > 0; o >>= 1) sum += __shfl_xor_sync(0xffffffffu, sum, o);
        float inv = __frcp_rn(sum);
        #pragma unroll
        for (int m = 0; m < 7; m++) {
            int kj = lane + 32 * m;
            if (kj < TOK) Ps[warp * 200 + kj] = p[m] * inv;
        }
        __syncwarp();

        // P . V : lane owns channels (2*lane, 2*lane+1)
        float o0 = 0.f, o1 = 0.f;
        #pragma unroll 4
        for (int kj = 0; kj < TOK; kj++) {
            float pp = Ps[warp * 200 + kj];
            float2 vf = __half22float2(vs2[kj * 32 + lane]);
            o0 = fmaf(pp, vf.x, o0);
            o1 = fmaf(pp, vf.y, o1);
        }
        __half* orow = attout + ((size_t)(bw * TOK + qi)) * CDIM + nh * HD;
        *(__half2*)(orow + 2 * lane) = __floats2half2_rn(o0, o1);
        __syncwarp();
    }
}

// ---------------- launch ----------------
extern "C" void kernel_launch(void* const* d_in, const int* in_sizes, int n_in,
                              void* d_out, int out_size) {
    const float* x       = (const float*)d_in[0];
    const float* ln1_g   = (const float*)d_in[1];
    const float* ln1_b   = (const float*)d_in[2];
    const float* w_qkv   = (const float*)d_in[3];
    const float* b_qkv   = (const float*)d_in[4];
    const float* w_proj  = (const float*)d_in[5];
    const float* b_proj  = (const float*)d_in[6];
    const float* relh    = (const float*)d_in[7];
    const float* relw    = (const float*)d_in[8];
    const float* ln2_g   = (const float*)d_in[9];
    const float* ln2_b   = (const float*)d_in[10];
    const float* w_fc1   = (const float*)d_in[11];
    const float* b_fc1   = (const float*)d_in[12];
    const float* w_fc2   = (const float*)d_in[13];
    const float* b_fc2   = (const float*)d_in[14];
    float* out = (float*)d_out;

    __half *win, *qkv, *att, *yln, *y1, *wqkv, *wproj, *wfc1, *wfc2;
    float *x2;
    cudaGetSymbolAddress((void**)&win, g_win);
    cudaGetSymbolAddress((void**)&qkv, g_qkv);
    cudaGetSymbolAddress((void**)&att, g_att);
    cudaGetSymbolAddress((void**)&x2,  g_x2);
    cudaGetSymbolAddress((void**)&yln, g_yln);
    cudaGetSymbolAddress((void**)&y1,  g_y1);
    cudaGetSymbolAddress((void**)&wqkv,  g_wqkv);
    cudaGetSymbolAddress((void**)&wproj, g_wproj);
    cudaGetSymbolAddress((void**)&wfc1,  g_wfc1);
    cudaGetSymbolAddress((void**)&wfc2,  g_wfc2);

    cudaFuncSetAttribute(attn_kernel, cudaFuncAttributeMaxDynamicSharedMemorySize, ATTN_SMEM_BYTES);
    cudaFuncSetAttribute(hgemm<0>, cudaFuncAttributeMaxDynamicSharedMemorySize, GEMM_SMEM_BYTES);
    cudaFuncSetAttribute(hgemm<1>, cudaFuncAttributeMaxDynamicSharedMemorySize, GEMM_SMEM_BYTES);
    cudaFuncSetAttribute(hgemm<2>, cudaFuncAttributeMaxDynamicSharedMemorySize, GEMM_SMEM_BYTES);
    cudaFuncSetAttribute(hgemm<3>, cudaFuncAttributeMaxDynamicSharedMemorySize, GEMM_SMEM_BYTES);

    // (1) weights -> half2 interleaved
    int wtot = W1T + W2T + W3T + W4T;
    w2h_all_kernel<<<(wtot + 255) / 256, 256>>>(w_qkv, w_proj, w_fc1, w_fc2,
                                                wqkv, wproj, wfc1, wfc2);

    // (2) LN1 + window partition
    ln1_win_kernel<<<(ROWS_WIN * 32 + 255) / 256, 256>>>(x, ln1_g, ln1_b, win);

    // (3) QKV GEMM -> half
    hgemm<0><<<dim3(QKVN / 128, (ROWS_WIN + 127) / 128), 256, GEMM_SMEM_BYTES>>>(
        win, wqkv, b_qkv, nullptr, qkv, ROWS_WIN, QKVN, CDIM);

    // (4) attention
    attn_kernel<<<BW * NH, 256, ATTN_SMEM_BYTES>>>(qkv, relh, relw, att);

    // (5) proj + window reverse + residual -> f32
    hgemm<2><<<dim3(CDIM / 128, (ROWS_WIN + 127) / 128), 256, GEMM_SMEM_BYTES>>>(
        att, wproj, b_proj, x, x2, ROWS_WIN, CDIM, CDIM);

    // (6) LN2 -> half
    ln2_kernel<<<(ROWS_IMG * 32 + 255) / 256, 256>>>(x2, ln2_g, ln2_b, yln);

    // (7) fc1 + gelu -> half
    hgemm<1><<<dim3(FFN / 128, ROWS_IMG / 128), 256, GEMM_SMEM_BYTES>>>(
        yln, wfc1, b_fc1, nullptr, y1, ROWS_IMG, FFN, CDIM);

    // (8) fc2 + residual -> out f32
    hgemm<3><<<dim3(CDIM / 128, ROWS_IMG / 128), 256, GEMM_SMEM_BYTES>>>(
        y1, wfc2, b_fc2, x2, out, ROWS_IMG, CDIM, FFN);
}